// round 11
// baseline (speedup 1.0000x reference)
#include <cuda_runtime.h>
#include <cuda_fp16.h>
#include <cstdint>

#define BATCH 16
#define CH    128
#define HH    64
#define WW    64
#define HW    4096
#define CQ    16
#define CV    64
#define TT    1024
#define NEG_INF (-3.402823466e38f)

typedef unsigned long long ull;
typedef unsigned int u32;

// ---------------- scratch ----------------
__device__ float g_Wt[CQ * CH];
__device__ float g_Wp[CQ * CH];
__device__ float g_Wg[CV * CH];
__device__ float g_Wo[CH * CV];

__device__ __half d_theta_h[BATCH * HW * CQ];  // [b][s][16] fp16
__device__ __half d_phi_h[BATCH * TT * CQ];    // [b][t][16] fp16
__device__ __half d_gT_h[BATCH * CV * TT];     // [b][c][t]  fp16 transposed
__device__ __half d_o_h[BATCH * HW * CV];      // [b][s][64] fp16

// ---------------- helpers ----------------
__device__ __forceinline__ u32 h2u(float a, float b) {
    __half2 h = __floats2half2_rn(a, b);
    return *reinterpret_cast<u32*>(&h);
}
__device__ __forceinline__ u32 smem_u32(const void* p) {
    u32 a;
    asm("{ .reg .u64 t; cvta.to.shared.u64 t, %1; cvt.u32.u64 %0, t; }" : "=r"(a) : "l"(p));
    return a;
}

// fp16 mma m16n8k16, f32 accumulate
__device__ __forceinline__ void mmaf16(float c[4], const u32 a[4], u32 b0, u32 b1) {
    asm("mma.sync.aligned.m16n8k16.row.col.f32.f16.f16.f32 "
        "{%0,%1,%2,%3}, {%4,%5,%6,%7}, {%8,%9}, {%0,%1,%2,%3};"
        : "+f"(c[0]), "+f"(c[1]), "+f"(c[2]), "+f"(c[3])
        : "r"(a[0]), "r"(a[1]), "r"(a[2]), "r"(a[3]), "r"(b0), "r"(b1));
}
__device__ __forceinline__ void ldm4(u32& r0, u32& r1, u32& r2, u32& r3, u32 addr) {
    asm volatile("ldmatrix.sync.aligned.m8n8.x4.shared.b16 {%0,%1,%2,%3}, [%4];"
                 : "=r"(r0), "=r"(r1), "=r"(r2), "=r"(r3) : "r"(addr));
}
__device__ __forceinline__ void ldm4t(u32& r0, u32& r1, u32& r2, u32& r3, u32 addr) {
    asm volatile("ldmatrix.sync.aligned.m8n8.x4.trans.shared.b16 {%0,%1,%2,%3}, [%4];"
                 : "=r"(r0), "=r"(r1), "=r"(r2), "=r"(r3) : "r"(addr));
}

__device__ __forceinline__ void cp16(u32 dst, const void* src) {
    asm volatile("cp.async.ca.shared.global [%0], [%1], 16;" :: "r"(dst), "l"(src));
}
__device__ __forceinline__ void cp_commit() { asm volatile("cp.async.commit_group;"); }
__device__ __forceinline__ void cp_wait0() { asm volatile("cp.async.wait_group 0;" ::: "memory"); }

// ---------------- spectral norm ----------------
__device__ __forceinline__ float block_reduce_sum_128(float v, float* sred) {
    int t = threadIdx.x;
    sred[t] = v;
    __syncthreads();
    #pragma unroll
    for (int s = 64; s > 0; s >>= 1) {
        if (t < s) sred[t] += sred[t + s];
        __syncthreads();
    }
    float r = sred[0];
    __syncthreads();
    return r;
}

__global__ void sn_kernel(const float* w_theta, const float* w_phi,
                          const float* w_g, const float* w_o,
                          const float* u_theta, const float* u_phi,
                          const float* u_g, const float* u_o) {
    __shared__ float sv[128];
    __shared__ float sred[128];
    const float* W; const float* u; float* Wn; int O, I;
    switch (blockIdx.x) {
        case 0:  W = w_theta; u = u_theta; Wn = g_Wt; O = CQ; I = CH; break;
        case 1:  W = w_phi;   u = u_phi;   Wn = g_Wp; O = CQ; I = CH; break;
        case 2:  W = w_g;     u = u_g;     Wn = g_Wg; O = CV; I = CH; break;
        default: W = w_o;     u = u_o;     Wn = g_Wo; O = CH; I = CV; break;
    }
    int t = threadIdx.x;
    float vr = 0.f;
    if (t < I) { for (int o = 0; o < O; o++) vr += u[o] * W[o * I + t]; }
    float nv2 = block_reduce_sum_128((t < I) ? vr * vr : 0.f, sred);
    float inv = 1.f / fmaxf(sqrtf(nv2), 1e-12f);
    if (t < I) sv[t] = vr * inv;
    __syncthreads();
    float ur = 0.f;
    if (t < O) { for (int i = 0; i < I; i++) ur += sv[i] * W[t * I + i]; }
    float nu2 = block_reduce_sum_128((t < O) ? ur * ur : 0.f, sred);
    float invu = 1.f / fmaxf(sqrtf(nu2), 1e-12f);
    float sigma = block_reduce_sum_128((t < O) ? ur * ur * invu : 0.f, sred);
    float wscale = 1.f / sigma;
    for (int k = t; k < O * I; k += 128) Wn[k] = W[k] * wscale;
}

// ---------------- fused input conv (theta | phi | g) via fp16 mma ----------------
#define XROW 272
#define SM_X 0
#define SM_W (128 * XROW)
#define CONV_SMEM (SM_W + 96 * XROW)

__global__ __launch_bounds__(256) void fusedconv_kernel(const float* __restrict__ x) {
    extern __shared__ char smc[];
    const u32 sXu = smem_u32(smc) + SM_X;
    const u32 sWu = smem_u32(smc) + SM_W;
    const int tid = threadIdx.x;
    const int w = tid >> 5, lane = tid & 31;
    const int b = blockIdx.x >> 5, j = blockIdx.x & 31;
    const int s0 = j * 128;

    for (int i = tid; i < 96 * 16; i += 256) {
        int out = i >> 4, seg = i & 15;
        const float* src;
        if (out < 16)      src = g_Wt + out * CH + seg * 8;
        else if (out < 32) src = g_Wp + (out - 16) * CH + seg * 8;
        else               src = g_Wg + (out - 32) * CH + seg * 8;
        float4 f0 = *(const float4*)src;
        float4 f1 = *(const float4*)(src + 4);
        uint4 v = make_uint4(h2u(f0.x, f0.y), h2u(f0.z, f0.w),
                             h2u(f1.x, f1.y), h2u(f1.z, f1.w));
        asm volatile("st.shared.v4.b32 [%0], {%1,%2,%3,%4};"
                     :: "r"(sWu + (u32)(out * XROW + seg * 16)),
                        "r"(v.x), "r"(v.y), "r"(v.z), "r"(v.w) : "memory");
    }
    for (int i = tid; i < 128 * 32; i += 256) {
        int ch = i >> 5, seg = i & 31;
        float4 f = *(const float4*)&x[((size_t)b * CH + ch) * HW + s0 + seg * 4];
        u32 h0 = h2u(f.x, f.y), h1 = h2u(f.z, f.w);
        asm volatile("st.shared.v2.b32 [%0], {%1,%2};"
                     :: "r"(sXu + (u32)(ch * XROW + seg * 8)), "r"(h0), "r"(h1) : "memory");
    }
    __syncthreads();

    const int jj = lane & 7, grp = lane >> 3;
    const u32 aBase = sXu + (u32)((((grp & 2) ? 8 : 0) + jj) * XROW
                                  + (16 * w + ((grp & 1) ? 8 : 0)) * 2);
    u32 bBase[6];
    #pragma unroll
    for (int np = 0; np < 6; np++)
        bBase[np] = sWu + (u32)((np * 16 + ((grp >> 1) ? 8 : 0) + jj) * XROW
                                + ((grp & 1) ? 16 : 0));

    float c[12][4];
    #pragma unroll
    for (int nt = 0; nt < 12; nt++)
        c[nt][0] = c[nt][1] = c[nt][2] = c[nt][3] = 0.f;

    #pragma unroll
    for (int t = 0; t < 8; t++) {
        u32 a[4];
        ldm4t(a[0], a[1], a[2], a[3], aBase + (u32)(t * 16 * XROW));
        #pragma unroll
        for (int np = 0; np < 6; np++) {
            u32 b0, b1, b2, b3;
            ldm4(b0, b1, b2, b3, bBase[np] + (u32)(t * 32));
            mmaf16(c[2 * np],     a, b0, b1);
            mmaf16(c[2 * np + 1], a, b2, b3);
        }
    }
    __syncthreads();

    const int g = lane >> 2, l = lane & 3;
    const int pxA = 16 * w + g;
    #pragma unroll
    for (int nt = 0; nt < 12; nt++) {
        u32 lo = h2u(c[nt][0], c[nt][1]);
        u32 hi = h2u(c[nt][2], c[nt][3]);
        asm volatile("st.shared.b32 [%0], %1;"
                     :: "r"(sXu + (u32)((pxA * 104 + nt * 8 + 2 * l) * 2)), "r"(lo) : "memory");
        asm volatile("st.shared.b32 [%0], %1;"
                     :: "r"(sXu + (u32)(((pxA + 8) * 104 + nt * 8 + 2 * l) * 2)), "r"(hi) : "memory");
    }
    __syncthreads();

    const __half* sCh = (const __half*)smc;
    {
        int px = tid >> 1, h = tid & 1;
        uint4 v = *(const uint4*)(sCh + px * 104 + h * 8);
        *(uint4*)&d_theta_h[((size_t)b * HW + s0 + px) * CQ + h * 8] = v;
    }
    if (tid < 64) {
        int wp = tid >> 1, h = tid & 1;
        int off = 16 + h * 8;
        const __half2* p0 = (const __half2*)(sCh + (2 * wp) * 104 + off);
        const __half2* p1 = (const __half2*)(sCh + (2 * wp + 1) * 104 + off);
        const __half2* p2 = (const __half2*)(sCh + (64 + 2 * wp) * 104 + off);
        const __half2* p3 = (const __half2*)(sCh + (65 + 2 * wp) * 104 + off);
        __half2 r[4];
        #pragma unroll
        for (int k = 0; k < 4; k++)
            r[k] = __hmax2(__hmax2(p0[k], p1[k]), __hmax2(p2[k], p3[k]));
        *(uint4*)&d_phi_h[((size_t)b * TT + j * 32 + wp) * CQ + h * 8] = *(uint4*)r;
    }
    if (tid < 128) {
        int ch = tid >> 1, wh = (tid & 1) * 16;
        __half2 outv[8];
        #pragma unroll
        for (int k2 = 0; k2 < 8; k2++) {
            __half v[2];
            #pragma unroll
            for (int u = 0; u < 2; u++) {
                int wp = wh + k2 * 2 + u;
                __half a0 = sCh[(2 * wp) * 104 + 32 + ch];
                __half a1 = sCh[(2 * wp + 1) * 104 + 32 + ch];
                __half a2 = sCh[(64 + 2 * wp) * 104 + 32 + ch];
                __half a3 = sCh[(65 + 2 * wp) * 104 + 32 + ch];
                v[u] = __hmax(__hmax(a0, a1), __hmax(a2, a3));
            }
            outv[k2] = __halves2half2(v[0], v[1]);
        }
        __half* dst = &d_gT_h[((size_t)b * CV + ch) * TT + j * 32 + wh];
        #pragma unroll
        for (int k2 = 0; k2 < 8; k2++) ((__half2*)dst)[k2] = outv[k2];
    }
}

// ---------------- attention: fp16 m16n8k16 flash, cp.async double-buffered ----
#define KSW 8
#define VSW 36
#define KSTG (64 * KSW)
#define VSTG (64 * VSW)
__global__ __launch_bounds__(256, 2) void attn_mma_kernel() {
    __shared__ u32 sK[2 * KSTG];
    __shared__ u32 sV[2 * VSTG];
    const int tid = threadIdx.x;
    const int w = tid >> 5, lane = tid & 31;
    const int g = lane >> 2, l = lane & 3;
    const int qbase = blockIdx.x * 128 + w * 16;
    const int b = (int)((blockIdx.x * 128) >> 12);
    const __half* phib = &d_phi_h[(size_t)(b << 10) * CQ];
    const __half* gTb  = &d_gT_h[(size_t)b * CV * TT];

    const u32 kbase = (u32)__cvta_generic_to_shared(sK);
    const u32 vbase = (u32)__cvta_generic_to_shared(sV);

    u32 qh[4];
    {
        const u32* q0 = (const u32*)&d_theta_h[(size_t)(qbase + g) * CQ];
        const u32* q1 = (const u32*)&d_theta_h[(size_t)(qbase + g + 8) * CQ];
        qh[0] = q0[l];     qh[1] = q1[l];
        qh[2] = q0[l + 4]; qh[3] = q1[l + 4];
    }

    float o[8][4];
    #pragma unroll
    for (int nt = 0; nt < 8; nt++)
        #pragma unroll
        for (int jj = 0; jj < 4; jj++) o[nt][jj] = 0.f;
    float mA = NEG_INF, mB = NEG_INF, lA = 0.f, lB = 0.f;

    auto fill = [&](int stage, int c0) {
        if (tid < 128) {
            int row = tid >> 1, part = tid & 1;
            cp16(kbase + (u32)((stage * KSTG + row * KSW + part * 4) * 4),
                 phib + (c0 + row) * CQ + part * 8);
        }
        #pragma unroll
        for (int i = 0; i < 2; i++) {
            int idx = tid * 2 + i;
            int c = idx >> 3, t8 = idx & 7;
            cp16(vbase + (u32)((stage * VSTG + c * VSW + t8 * 4) * 4),
                 gTb + (size_t)c * TT + c0 + t8 * 8);
        }
        cp_commit();
    };

    fill(0, 0);
    cp_wait0();
    __syncthreads();

    for (int c0 = 0; c0 < TT; c0 += 64) {
        int stage = (c0 >> 6) & 1;
        const u32* cK = sK + stage * KSTG;
        const u32* cV = sV + stage * VSTG;

        if (c0 + 64 < TT) fill(stage ^ 1, c0 + 64);

        float c[8][4];
        #pragma unroll
        for (int nt = 0; nt < 8; nt++) {
            c[nt][0] = c[nt][1] = c[nt][2] = c[nt][3] = 0.f;
            int kr = (nt * 8 + g) * KSW;
            mmaf16(c[nt], qh, cK[kr + l], cK[kr + l + 4]);
        }

        float cmA = NEG_INF, cmB = NEG_INF;
        #pragma unroll
        for (int nt = 0; nt < 8; nt++) {
            cmA = fmaxf(cmA, fmaxf(c[nt][0], c[nt][1]));
            cmB = fmaxf(cmB, fmaxf(c[nt][2], c[nt][3]));
        }
        cmA = fmaxf(cmA, __shfl_xor_sync(0xffffffffu, cmA, 1));
        cmA = fmaxf(cmA, __shfl_xor_sync(0xffffffffu, cmA, 2));
        cmB = fmaxf(cmB, __shfl_xor_sync(0xffffffffu, cmB, 1));
        cmB = fmaxf(cmB, __shfl_xor_sync(0xffffffffu, cmB, 2));
        float nmA = fmaxf(mA, cmA), nmB = fmaxf(mB, cmB);
        float sA = __expf(mA - nmA), sB = __expf(mB - nmB);
        mA = nmA; mB = nmB;
        lA *= sA; lB *= sB;

        u32 pa[4][4];
        #pragma unroll
        for (int nt = 0; nt < 8; nt++) {
            o[nt][0] *= sA; o[nt][1] *= sA; o[nt][2] *= sB; o[nt][3] *= sB;
            float p0 = __expf(c[nt][0] - mA);
            float p1 = __expf(c[nt][1] - mA);
            float p2 = __expf(c[nt][2] - mB);
            float p3 = __expf(c[nt][3] - mB);
            lA += p0 + p1; lB += p2 + p3;
            int kb = nt >> 1, hi = nt & 1;
            pa[kb][hi * 2]     = h2u(p0, p1);
            pa[kb][hi * 2 + 1] = h2u(p2, p3);
        }

        #pragma unroll
        for (int kb = 0; kb < 4; kb++) {
            #pragma unroll
            for (int nt = 0; nt < 8; nt++) {
                int vr = (nt * 8 + g) * VSW + kb * 8 + l;
                mmaf16(o[nt], pa[kb], cV[vr], cV[vr + 4]);
            }
        }

        cp_wait0();
        __syncthreads();
    }

    lA += __shfl_xor_sync(0xffffffffu, lA, 1);
    lA += __shfl_xor_sync(0xffffffffu, lA, 2);
    lB += __shfl_xor_sync(0xffffffffu, lB, 1);
    lB += __shfl_xor_sync(0xffffffffu, lB, 2);
    float iA = 1.f / lA, iB = 1.f / lB;
    #pragma unroll
    for (int nt = 0; nt < 8; nt++) {
        u32 r0 = h2u(o[nt][0] * iA, o[nt][1] * iA);
        u32 r1 = h2u(o[nt][2] * iB, o[nt][3] * iB);
        *(u32*)&d_o_h[(size_t)(qbase + g) * CV + nt * 8 + 2 * l] = r0;
        *(u32*)&d_o_h[(size_t)(qbase + g + 8) * CV + nt * 8 + 2 * l] = r1;
    }
}

// ---------------- output conv + residual via fp16 mma (64-px tiles) ----------------
// Grid 1024 = (b, j:64-px tile). 256 thr / 8 warps: 4 m-warps x 2 n-halves.
// A = o [64 px][64 k] fp16, B = Wo [128 out][64 k] fp16, both plain ldmatrix.
// Bounce stride 68 floats = 272 B (16-B aligned; banks (8l+g) all distinct).
#define OROWB 144                  // 72 halfs per row
#define OBSTRIDE 68
__global__ __launch_bounds__(256) void oconv_mma_kernel(const float* __restrict__ x,
                                                        const float* __restrict__ gptr,
                                                        float* __restrict__ out) {
    __shared__ __align__(16) char smc[64 * OROWB + 128 * OROWB];  // A 9216 + W 18432
    const u32 sOu = smem_u32(smc);
    const u32 sWu = sOu + 64 * OROWB;
    float* sB = (float*)smc;       // bounce [64 ch][68] f32 = 17.4 KB (reuse)
    const int tid = threadIdx.x;
    const int w = tid >> 5, lane = tid & 31;
    const int mw = w & 3, nh = w >> 2;
    const int b = blockIdx.x >> 6, j = blockIdx.x & 63;
    const int s0 = j * 64;

    // fill o smem: [64 px][64 k] fp16 (cp.async, 2 per thread)
    #pragma unroll
    for (int i = 0; i < 2; i++) {
        int idx = tid * 2 + i;
        int px = idx >> 3, seg = idx & 7;
        cp16(sOu + (u32)(px * OROWB + seg * 16),
             d_o_h + ((size_t)b * HW + s0 + px) * CV + seg * 8);
    }
    cp_commit();
    // fill W smem: Wo [128 out][64 k] f32 -> fp16
    for (int i = tid; i < 128 * 8; i += 256) {
        int o8 = i >> 3, seg = i & 7;
        const float* src = g_Wo + o8 * CV + seg * 8;
        float4 f0 = *(const float4*)src;
        float4 f1 = *(const float4*)(src + 4);
        uint4 v = make_uint4(h2u(f0.x, f0.y), h2u(f0.z, f0.w),
                             h2u(f1.x, f1.y), h2u(f1.z, f1.w));
        asm volatile("st.shared.v4.b32 [%0], {%1,%2,%3,%4};"
                     :: "r"(sWu + (u32)(o8 * OROWB + seg * 16)),
                        "r"(v.x), "r"(v.y), "r"(v.z), "r"(v.w) : "memory");
    }
    cp_wait0();
    __syncthreads();

    const int jj = lane & 7, grp = lane >> 3;
    const u32 aBase = sOu + (u32)((16 * mw + ((grp & 1) ? 8 : 0) + jj) * OROWB
                                  + ((grp & 2) ? 16 : 0));
    u32 bBase[4];
    #pragma unroll
    for (int np = 0; np < 4; np++)
        bBase[np] = sWu + (u32)((nh * 64 + np * 16 + ((grp >> 1) ? 8 : 0) + jj) * OROWB
                                + ((grp & 1) ? 16 : 0));

    float c[8][4];
    #pragma unroll
    for (int nt = 0; nt < 8; nt++)
        c[nt][0] = c[nt][1] = c[nt][2] = c[nt][3] = 0.f;

    #pragma unroll
    for (int t = 0; t < 4; t++) {
        u32 a[4];
        ldm4(a[0], a[1], a[2], a[3], aBase + (u32)(t * 32));
        #pragma unroll
        for (int np = 0; np < 4; np++) {
            u32 b0, b1, b2, b3;
            ldm4(b0, b1, b2, b3, bBase[np] + (u32)(t * 32));
            mmaf16(c[2 * np],     a, b0, b1);
            mmaf16(c[2 * np + 1], a, b2, b3);
        }
    }
    __syncthreads();

    const float gamma = *gptr;
    const int g = lane >> 2, l = lane & 3;
    #pragma unroll
    for (int h = 0; h < 2; h++) {
        if (nh == h) {
            #pragma unroll
            for (int i = 0; i < 8; i++) {
                int np = i >> 1, hi = i & 1;
                int cl = np * 16 + hi * 8 + 2 * l;
                sB[cl * OBSTRIDE + 16 * mw + g]           = c[i][0];
                sB[(cl + 1) * OBSTRIDE + 16 * mw + g]     = c[i][1];
                sB[cl * OBSTRIDE + 16 * mw + g + 8]       = c[i][2];
                sB[(cl + 1) * OBSTRIDE + 16 * mw + g + 8] = c[i][3];
            }
        }
        __syncthreads();
        // coalesced write: out = gamma*C + x  (1024 float4 = 64 ch x 16 groups)
        #pragma unroll
        for (int k = 0; k < 4; k++) {
            int flat = k * 256 + tid;
            int cc = flat >> 4, pxg = flat & 15;
            float4 v = *(const float4*)&sB[cc * OBSTRIDE + pxg * 4];
            size_t idx = ((size_t)(b * CH) + 64 * h + cc) * HW + s0 + pxg * 4;
            float4 xv = *(const float4*)&x[idx];
            *(float4*)&out[idx] = make_float4(gamma * v.x + xv.x, gamma * v.y + xv.y,
                                              gamma * v.z + xv.z, gamma * v.w + xv.w);
        }
        __syncthreads();
    }
}

// ---------------- launch ----------------
extern "C" void kernel_launch(void* const* d_in, const int* in_sizes, int n_in,
                              void* d_out, int out_size) {
    const float* x       = (const float*)d_in[0];
    const float* w_theta = (const float*)d_in[1];
    const float* w_phi   = (const float*)d_in[2];
    const float* w_g     = (const float*)d_in[3];
    const float* w_o     = (const float*)d_in[4];
    const float* u_theta = (const float*)d_in[5];
    const float* u_phi   = (const float*)d_in[6];
    const float* u_g     = (const float*)d_in[7];
    const float* u_o     = (const float*)d_in[8];
    const float* gamma   = (const float*)d_in[9];
    float* out = (float*)d_out;

    cudaFuncSetAttribute(fusedconv_kernel, cudaFuncAttributeMaxDynamicSharedMemorySize, CONV_SMEM);

    sn_kernel<<<4, 128>>>(w_theta, w_phi, w_g, w_o, u_theta, u_phi, u_g, u_o);
    fusedconv_kernel<<<512, 256, CONV_SMEM>>>(x);
    attn_mma_kernel<<<512, 256>>>();
    oconv_mma_kernel<<<1024, 256>>>(x, gamma, out);
}

// round 12
// speedup vs baseline: 1.0914x; 1.0914x over previous
#include <cuda_runtime.h>
#include <cuda_fp16.h>
#include <cstdint>

#define BATCH 16
#define CH    128
#define HH    64
#define WW    64
#define HW    4096
#define CQ    16
#define CV    64
#define TT    1024
#define NEG_INF (-3.402823466e38f)

typedef unsigned long long ull;
typedef unsigned int u32;

// ---------------- scratch ----------------
__device__ float g_Wt[CQ * CH];
__device__ float g_Wp[CQ * CH];
__device__ float g_Wg[CV * CH];
__device__ float g_Wo[CH * CV];

__device__ __half d_theta_h[BATCH * HW * CQ];  // [b][s][16] fp16
__device__ __half d_phi_h[BATCH * TT * CQ];    // [b][t][16] fp16
__device__ __half d_gT_h[BATCH * CV * TT];     // [b][c][t]  fp16 transposed

// ---------------- helpers ----------------
__device__ __forceinline__ u32 h2u(float a, float b) {
    __half2 h = __floats2half2_rn(a, b);
    return *reinterpret_cast<u32*>(&h);
}
__device__ __forceinline__ u32 smem_u32(const void* p) {
    u32 a;
    asm("{ .reg .u64 t; cvta.to.shared.u64 t, %1; cvt.u32.u64 %0, t; }" : "=r"(a) : "l"(p));
    return a;
}

// fp16 mma m16n8k16, f32 accumulate
__device__ __forceinline__ void mmaf16(float c[4], const u32 a[4], u32 b0, u32 b1) {
    asm("mma.sync.aligned.m16n8k16.row.col.f32.f16.f16.f32 "
        "{%0,%1,%2,%3}, {%4,%5,%6,%7}, {%8,%9}, {%0,%1,%2,%3};"
        : "+f"(c[0]), "+f"(c[1]), "+f"(c[2]), "+f"(c[3])
        : "r"(a[0]), "r"(a[1]), "r"(a[2]), "r"(a[3]), "r"(b0), "r"(b1));
}
__device__ __forceinline__ void ldm4(u32& r0, u32& r1, u32& r2, u32& r3, u32 addr) {
    asm volatile("ldmatrix.sync.aligned.m8n8.x4.shared.b16 {%0,%1,%2,%3}, [%4];"
                 : "=r"(r0), "=r"(r1), "=r"(r2), "=r"(r3) : "r"(addr));
}
__device__ __forceinline__ void ldm4t(u32& r0, u32& r1, u32& r2, u32& r3, u32 addr) {
    asm volatile("ldmatrix.sync.aligned.m8n8.x4.trans.shared.b16 {%0,%1,%2,%3}, [%4];"
                 : "=r"(r0), "=r"(r1), "=r"(r2), "=r"(r3) : "r"(addr));
}

__device__ __forceinline__ void cp16(u32 dst, const void* src) {
    asm volatile("cp.async.ca.shared.global [%0], [%1], 16;" :: "r"(dst), "l"(src));
}
__device__ __forceinline__ void cp_commit() { asm volatile("cp.async.commit_group;"); }
__device__ __forceinline__ void cp_wait0() { asm volatile("cp.async.wait_group 0;" ::: "memory"); }

// ---------------- spectral norm ----------------
__device__ __forceinline__ float block_reduce_sum_128(float v, float* sred) {
    int t = threadIdx.x;
    sred[t] = v;
    __syncthreads();
    #pragma unroll
    for (int s = 64; s > 0; s >>= 1) {
        if (t < s) sred[t] += sred[t + s];
        __syncthreads();
    }
    float r = sred[0];
    __syncthreads();
    return r;
}

__global__ void sn_kernel(const float* w_theta, const float* w_phi,
                          const float* w_g, const float* w_o,
                          const float* u_theta, const float* u_phi,
                          const float* u_g, const float* u_o) {
    __shared__ float sv[128];
    __shared__ float sred[128];
    const float* W; const float* u; float* Wn; int O, I;
    switch (blockIdx.x) {
        case 0:  W = w_theta; u = u_theta; Wn = g_Wt; O = CQ; I = CH; break;
        case 1:  W = w_phi;   u = u_phi;   Wn = g_Wp; O = CQ; I = CH; break;
        case 2:  W = w_g;     u = u_g;     Wn = g_Wg; O = CV; I = CH; break;
        default: W = w_o;     u = u_o;     Wn = g_Wo; O = CH; I = CV; break;
    }
    int t = threadIdx.x;
    float vr = 0.f;
    if (t < I) { for (int o = 0; o < O; o++) vr += u[o] * W[o * I + t]; }
    float nv2 = block_reduce_sum_128((t < I) ? vr * vr : 0.f, sred);
    float inv = 1.f / fmaxf(sqrtf(nv2), 1e-12f);
    if (t < I) sv[t] = vr * inv;
    __syncthreads();
    float ur = 0.f;
    if (t < O) { for (int i = 0; i < I; i++) ur += sv[i] * W[t * I + i]; }
    float nu2 = block_reduce_sum_128((t < O) ? ur * ur : 0.f, sred);
    float invu = 1.f / fmaxf(sqrtf(nu2), 1e-12f);
    float sigma = block_reduce_sum_128((t < O) ? ur * ur * invu : 0.f, sred);
    float wscale = 1.f / sigma;
    for (int k = t; k < O * I; k += 128) Wn[k] = W[k] * wscale;
}

// ---------------- fused input conv (theta | phi | g) via fp16 mma ----------------
#define XROW 272
#define SM_X 0
#define SM_W (128 * XROW)
#define CONV_SMEM (SM_W + 96 * XROW)

__global__ __launch_bounds__(256) void fusedconv_kernel(const float* __restrict__ x) {
    extern __shared__ char smc[];
    const u32 sXu = smem_u32(smc) + SM_X;
    const u32 sWu = smem_u32(smc) + SM_W;
    const int tid = threadIdx.x;
    const int w = tid >> 5, lane = tid & 31;
    const int b = blockIdx.x >> 5, j = blockIdx.x & 31;
    const int s0 = j * 128;

    for (int i = tid; i < 96 * 16; i += 256) {
        int out = i >> 4, seg = i & 15;
        const float* src;
        if (out < 16)      src = g_Wt + out * CH + seg * 8;
        else if (out < 32) src = g_Wp + (out - 16) * CH + seg * 8;
        else               src = g_Wg + (out - 32) * CH + seg * 8;
        float4 f0 = *(const float4*)src;
        float4 f1 = *(const float4*)(src + 4);
        uint4 v = make_uint4(h2u(f0.x, f0.y), h2u(f0.z, f0.w),
                             h2u(f1.x, f1.y), h2u(f1.z, f1.w));
        asm volatile("st.shared.v4.b32 [%0], {%1,%2,%3,%4};"
                     :: "r"(sWu + (u32)(out * XROW + seg * 16)),
                        "r"(v.x), "r"(v.y), "r"(v.z), "r"(v.w) : "memory");
    }
    for (int i = tid; i < 128 * 32; i += 256) {
        int ch = i >> 5, seg = i & 31;
        float4 f = *(const float4*)&x[((size_t)b * CH + ch) * HW + s0 + seg * 4];
        u32 h0 = h2u(f.x, f.y), h1 = h2u(f.z, f.w);
        asm volatile("st.shared.v2.b32 [%0], {%1,%2};"
                     :: "r"(sXu + (u32)(ch * XROW + seg * 8)), "r"(h0), "r"(h1) : "memory");
    }
    __syncthreads();

    const int jj = lane & 7, grp = lane >> 3;
    const u32 aBase = sXu + (u32)((((grp & 2) ? 8 : 0) + jj) * XROW
                                  + (16 * w + ((grp & 1) ? 8 : 0)) * 2);
    u32 bBase[6];
    #pragma unroll
    for (int np = 0; np < 6; np++)
        bBase[np] = sWu + (u32)((np * 16 + ((grp >> 1) ? 8 : 0) + jj) * XROW
                                + ((grp & 1) ? 16 : 0));

    float c[12][4];
    #pragma unroll
    for (int nt = 0; nt < 12; nt++)
        c[nt][0] = c[nt][1] = c[nt][2] = c[nt][3] = 0.f;

    #pragma unroll
    for (int t = 0; t < 8; t++) {
        u32 a[4];
        ldm4t(a[0], a[1], a[2], a[3], aBase + (u32)(t * 16 * XROW));
        #pragma unroll
        for (int np = 0; np < 6; np++) {
            u32 b0, b1, b2, b3;
            ldm4(b0, b1, b2, b3, bBase[np] + (u32)(t * 32));
            mmaf16(c[2 * np],     a, b0, b1);
            mmaf16(c[2 * np + 1], a, b2, b3);
        }
    }
    __syncthreads();

    const int g = lane >> 2, l = lane & 3;
    const int pxA = 16 * w + g;
    #pragma unroll
    for (int nt = 0; nt < 12; nt++) {
        u32 lo = h2u(c[nt][0], c[nt][1]);
        u32 hi = h2u(c[nt][2], c[nt][3]);
        asm volatile("st.shared.b32 [%0], %1;"
                     :: "r"(sXu + (u32)((pxA * 104 + nt * 8 + 2 * l) * 2)), "r"(lo) : "memory");
        asm volatile("st.shared.b32 [%0], %1;"
                     :: "r"(sXu + (u32)(((pxA + 8) * 104 + nt * 8 + 2 * l) * 2)), "r"(hi) : "memory");
    }
    __syncthreads();

    const __half* sCh = (const __half*)smc;
    {
        int px = tid >> 1, h = tid & 1;
        uint4 v = *(const uint4*)(sCh + px * 104 + h * 8);
        *(uint4*)&d_theta_h[((size_t)b * HW + s0 + px) * CQ + h * 8] = v;
    }
    if (tid < 64) {
        int wp = tid >> 1, h = tid & 1;
        int off = 16 + h * 8;
        const __half2* p0 = (const __half2*)(sCh + (2 * wp) * 104 + off);
        const __half2* p1 = (const __half2*)(sCh + (2 * wp + 1) * 104 + off);
        const __half2* p2 = (const __half2*)(sCh + (64 + 2 * wp) * 104 + off);
        const __half2* p3 = (const __half2*)(sCh + (65 + 2 * wp) * 104 + off);
        __half2 r[4];
        #pragma unroll
        for (int k = 0; k < 4; k++)
            r[k] = __hmax2(__hmax2(p0[k], p1[k]), __hmax2(p2[k], p3[k]));
        *(uint4*)&d_phi_h[((size_t)b * TT + j * 32 + wp) * CQ + h * 8] = *(uint4*)r;
    }
    if (tid < 128) {
        int ch = tid >> 1, wh = (tid & 1) * 16;
        __half2 outv[8];
        #pragma unroll
        for (int k2 = 0; k2 < 8; k2++) {
            __half v[2];
            #pragma unroll
            for (int u = 0; u < 2; u++) {
                int wp = wh + k2 * 2 + u;
                __half a0 = sCh[(2 * wp) * 104 + 32 + ch];
                __half a1 = sCh[(2 * wp + 1) * 104 + 32 + ch];
                __half a2 = sCh[(64 + 2 * wp) * 104 + 32 + ch];
                __half a3 = sCh[(65 + 2 * wp) * 104 + 32 + ch];
                v[u] = __hmax(__hmax(a0, a1), __hmax(a2, a3));
            }
            outv[k2] = __halves2half2(v[0], v[1]);
        }
        __half* dst = &d_gT_h[((size_t)b * CV + ch) * TT + j * 32 + wh];
        #pragma unroll
        for (int k2 = 0; k2 < 8; k2++) ((__half2*)dst)[k2] = outv[k2];
    }
}

// ---- attention + fused output conv + residual --------------------------------
// smem: sK 4KB | sV 18.4KB | sWo 18.4KB ; after mainloop sK∪sV reused as bounce.
#define KSW 8
#define VSW 36
#define KSTG (64 * KSW)
#define VSTG (64 * VSW)
#define OROWB 144
#define ATTN_SMEM_BYTES (2 * KSTG * 4 + 2 * VSTG * 4 + 128 * OROWB)  // 40960

__global__ __launch_bounds__(256, 2) void attn_fused_kernel(const float* __restrict__ x,
                                                            const float* __restrict__ gptr,
                                                            float* __restrict__ out) {
    __shared__ __align__(16) char sbuf[ATTN_SMEM_BYTES];
    u32* sK = (u32*)sbuf;
    u32* sV = sK + 2 * KSTG;
    const u32 kbase = smem_u32(sbuf);
    const u32 vbase = kbase + 2 * KSTG * 4;
    const u32 wobase = kbase + 2 * KSTG * 4 + 2 * VSTG * 4;
    float* sB = (float*)sbuf;   // bounce, overlays sK+sV after mainloop

    const int tid = threadIdx.x;
    const int w = tid >> 5, lane = tid & 31;
    const int g = lane >> 2, l = lane & 3;
    const int qbase = blockIdx.x * 128 + w * 16;
    const int b = (int)((blockIdx.x * 128) >> 12);
    const int s0 = (blockIdx.x * 128) & 4095;
    const __half* phib = &d_phi_h[(size_t)(b << 10) * CQ];
    const __half* gTb  = &d_gT_h[(size_t)b * CV * TT];

    // fill Wo smem: [128 out][64 k] f32 -> fp16, row stride 144B
    for (int i = tid; i < 128 * 8; i += 256) {
        int o8 = i >> 3, seg = i & 7;
        const float* src = g_Wo + o8 * CV + seg * 8;
        float4 f0 = *(const float4*)src;
        float4 f1 = *(const float4*)(src + 4);
        uint4 v = make_uint4(h2u(f0.x, f0.y), h2u(f0.z, f0.w),
                             h2u(f1.x, f1.y), h2u(f1.z, f1.w));
        asm volatile("st.shared.v4.b32 [%0], {%1,%2,%3,%4};"
                     :: "r"(wobase + (u32)(o8 * OROWB + seg * 16)),
                        "r"(v.x), "r"(v.y), "r"(v.z), "r"(v.w) : "memory");
    }

    u32 qh[4];
    {
        const u32* q0 = (const u32*)&d_theta_h[(size_t)(qbase + g) * CQ];
        const u32* q1 = (const u32*)&d_theta_h[(size_t)(qbase + g + 8) * CQ];
        qh[0] = q0[l];     qh[1] = q1[l];
        qh[2] = q0[l + 4]; qh[3] = q1[l + 4];
    }

    float o[8][4];
    #pragma unroll
    for (int nt = 0; nt < 8; nt++)
        #pragma unroll
        for (int jj = 0; jj < 4; jj++) o[nt][jj] = 0.f;
    float mA = NEG_INF, mB = NEG_INF, lA = 0.f, lB = 0.f;

    auto fill = [&](int stage, int c0) {
        if (tid < 128) {
            int row = tid >> 1, part = tid & 1;
            cp16(kbase + (u32)((stage * KSTG + row * KSW + part * 4) * 4),
                 phib + (c0 + row) * CQ + part * 8);
        }
        #pragma unroll
        for (int i = 0; i < 2; i++) {
            int idx = tid * 2 + i;
            int c = idx >> 3, t8 = idx & 7;
            cp16(vbase + (u32)((stage * VSTG + c * VSW + t8 * 4) * 4),
                 gTb + (size_t)c * TT + c0 + t8 * 8);
        }
        cp_commit();
    };

    fill(0, 0);
    cp_wait0();
    __syncthreads();

    for (int c0 = 0; c0 < TT; c0 += 64) {
        int stage = (c0 >> 6) & 1;
        const u32* cK = sK + stage * KSTG;
        const u32* cV = sV + stage * VSTG;

        if (c0 + 64 < TT) fill(stage ^ 1, c0 + 64);

        float c[8][4];
        #pragma unroll
        for (int nt = 0; nt < 8; nt++) {
            c[nt][0] = c[nt][1] = c[nt][2] = c[nt][3] = 0.f;
            int kr = (nt * 8 + g) * KSW;
            mmaf16(c[nt], qh, cK[kr + l], cK[kr + l + 4]);
        }

        float cmA = NEG_INF, cmB = NEG_INF;
        #pragma unroll
        for (int nt = 0; nt < 8; nt++) {
            cmA = fmaxf(cmA, fmaxf(c[nt][0], c[nt][1]));
            cmB = fmaxf(cmB, fmaxf(c[nt][2], c[nt][3]));
        }
        cmA = fmaxf(cmA, __shfl_xor_sync(0xffffffffu, cmA, 1));
        cmA = fmaxf(cmA, __shfl_xor_sync(0xffffffffu, cmA, 2));
        cmB = fmaxf(cmB, __shfl_xor_sync(0xffffffffu, cmB, 1));
        cmB = fmaxf(cmB, __shfl_xor_sync(0xffffffffu, cmB, 2));
        float nmA = fmaxf(mA, cmA), nmB = fmaxf(mB, cmB);
        float sA = __expf(mA - nmA), sB2 = __expf(mB - nmB);
        mA = nmA; mB = nmB;
        lA *= sA; lB *= sB2;

        u32 pa[4][4];
        #pragma unroll
        for (int nt = 0; nt < 8; nt++) {
            o[nt][0] *= sA; o[nt][1] *= sA; o[nt][2] *= sB2; o[nt][3] *= sB2;
            float p0 = __expf(c[nt][0] - mA);
            float p1 = __expf(c[nt][1] - mA);
            float p2 = __expf(c[nt][2] - mB);
            float p3 = __expf(c[nt][3] - mB);
            lA += p0 + p1; lB += p2 + p3;
            int kb = nt >> 1, hi = nt & 1;
            pa[kb][hi * 2]     = h2u(p0, p1);
            pa[kb][hi * 2 + 1] = h2u(p2, p3);
        }

        #pragma unroll
        for (int kb = 0; kb < 4; kb++) {
            #pragma unroll
            for (int nt = 0; nt < 8; nt++) {
                int vr = (nt * 8 + g) * VSW + kb * 8 + l;
                mmaf16(o[nt], pa[kb], cV[vr], cV[vr + 4]);
            }
        }

        cp_wait0();
        __syncthreads();
    }

    // ---- normalize o, build fp16 A-fragments (bit-identical to old d_o_h path) ----
    lA += __shfl_xor_sync(0xffffffffu, lA, 1);
    lA += __shfl_xor_sync(0xffffffffu, lA, 2);
    lB += __shfl_xor_sync(0xffffffffu, lB, 1);
    lB += __shfl_xor_sync(0xffffffffu, lB, 2);
    float iA = 1.f / lA, iB = 1.f / lB;
    u32 a2[4][4];
    #pragma unroll
    for (int kb = 0; kb < 4; kb++) {
        a2[kb][0] = h2u(o[2*kb][0] * iA,     o[2*kb][1] * iA);
        a2[kb][1] = h2u(o[2*kb][2] * iB,     o[2*kb][3] * iB);
        a2[kb][2] = h2u(o[2*kb + 1][0] * iA, o[2*kb + 1][1] * iA);
        a2[kb][3] = h2u(o[2*kb + 1][2] * iB, o[2*kb + 1][3] * iB);
    }

    // ---- fused output conv: out = gamma * (o_norm @ Wo^T) + x ----
    const float gamma = *gptr;
    const int jj = lane & 7, grp = lane >> 3;
    #pragma unroll
    for (int pp = 0; pp < 4; pp++) {       // 32-out-channel groups
        float c2[4][4];
        #pragma unroll
        for (int nt = 0; nt < 4; nt++)
            c2[nt][0] = c2[nt][1] = c2[nt][2] = c2[nt][3] = 0.f;
        #pragma unroll
        for (int t = 0; t < 4; t++) {
            #pragma unroll
            for (int np = 0; np < 2; np++) {
                u32 b0, b1, b2, b3;
                u32 baddr = wobase + (u32)((pp * 32 + np * 16 + ((grp >> 1) ? 8 : 0) + jj) * OROWB
                                           + ((grp & 1) ? 16 : 0) + t * 32);
                ldm4(b0, b1, b2, b3, baddr);
                mmaf16(c2[2 * np],     a2[t], b0, b1);
                mmaf16(c2[2 * np + 1], a2[t], b2, b3);
            }
        }
        // bounce [32 ch][132] f32
        #pragma unroll
        for (int nt = 0; nt < 4; nt++) {
            int cl = (nt >> 1) * 16 + (nt & 1) * 8 + 2 * l;
            sB[cl * 132 + 16 * w + g]           = c2[nt][0];
            sB[(cl + 1) * 132 + 16 * w + g]     = c2[nt][1];
            sB[cl * 132 + 16 * w + g + 8]       = c2[nt][2];
            sB[(cl + 1) * 132 + 16 * w + g + 8] = c2[nt][3];
        }
        __syncthreads();
        // coalesced write: 32 ch x 128 px = 1024 float4
        #pragma unroll
        for (int k = 0; k < 4; k++) {
            int flat = k * 256 + tid;
            int cc = flat >> 5, pxg = flat & 31;
            float4 v = *(const float4*)&sB[cc * 132 + pxg * 4];
            size_t idx = ((size_t)(b * CH) + pp * 32 + cc) * HW + s0 + pxg * 4;
            float4 xv = *(const float4*)&x[idx];
            *(float4*)&out[idx] = make_float4(gamma * v.x + xv.x, gamma * v.y + xv.y,
                                              gamma * v.z + xv.z, gamma * v.w + xv.w);
        }
        __syncthreads();
    }
}

// ---------------- launch ----------------
extern "C" void kernel_launch(void* const* d_in, const int* in_sizes, int n_in,
                              void* d_out, int out_size) {
    const float* x       = (const float*)d_in[0];
    const float* w_theta = (const float*)d_in[1];
    const float* w_phi   = (const float*)d_in[2];
    const float* w_g     = (const float*)d_in[3];
    const float* w_o     = (const float*)d_in[4];
    const float* u_theta = (const float*)d_in[5];
    const float* u_phi   = (const float*)d_in[6];
    const float* u_g     = (const float*)d_in[7];
    const float* u_o     = (const float*)d_in[8];
    const float* gamma   = (const float*)d_in[9];
    float* out = (float*)d_out;

    cudaFuncSetAttribute(fusedconv_kernel, cudaFuncAttributeMaxDynamicSharedMemorySize, CONV_SMEM);

    sn_kernel<<<4, 128>>>(w_theta, w_phi, w_g, w_o, u_theta, u_phi, u_g, u_o);
    fusedconv_kernel<<<512, 256, CONV_SMEM>>>(x);
    attn_fused_kernel<<<512, 256>>>(x, gamma, out);
}

// round 13
// speedup vs baseline: 1.2362x; 1.1327x over previous
#include <cuda_runtime.h>
#include <cuda_fp16.h>
#include <cstdint>

#define BATCH 16
#define CH    128
#define HH    64
#define WW    64
#define HW    4096
#define CQ    16
#define CV    64
#define TT    1024
#define NEG_INF (-3.402823466e38f)

typedef unsigned long long ull;
typedef unsigned int u32;

// ---------------- scratch ----------------
__device__ float g_Wt[CQ * CH];
__device__ float g_Wp[CQ * CH];
__device__ float g_Wg[CV * CH];
__device__ float g_Wo[CH * CV];

__device__ __half d_theta_h[BATCH * HW * CQ];  // [b][s][16] fp16
__device__ __half d_phi_h[BATCH * TT * CQ];    // [b][t][16] fp16
__device__ __half d_gT_h[BATCH * CV * TT];     // [b][c][t]  fp16 transposed

// ---------------- helpers ----------------
__device__ __forceinline__ u32 h2u(float a, float b) {
    __half2 h = __floats2half2_rn(a, b);
    return *reinterpret_cast<u32*>(&h);
}
__device__ __forceinline__ u32 smem_u32(const void* p) {
    u32 a;
    asm("{ .reg .u64 t; cvta.to.shared.u64 t, %1; cvt.u32.u64 %0, t; }" : "=r"(a) : "l"(p));
    return a;
}

// fp16 mma m16n8k16, f32 accumulate
__device__ __forceinline__ void mmaf16(float c[4], const u32 a[4], u32 b0, u32 b1) {
    asm("mma.sync.aligned.m16n8k16.row.col.f32.f16.f16.f32 "
        "{%0,%1,%2,%3}, {%4,%5,%6,%7}, {%8,%9}, {%0,%1,%2,%3};"
        : "+f"(c[0]), "+f"(c[1]), "+f"(c[2]), "+f"(c[3])
        : "r"(a[0]), "r"(a[1]), "r"(a[2]), "r"(a[3]), "r"(b0), "r"(b1));
}
__device__ __forceinline__ void ldm4(u32& r0, u32& r1, u32& r2, u32& r3, u32 addr) {
    asm volatile("ldmatrix.sync.aligned.m8n8.x4.shared.b16 {%0,%1,%2,%3}, [%4];"
                 : "=r"(r0), "=r"(r1), "=r"(r2), "=r"(r3) : "r"(addr));
}
__device__ __forceinline__ void ldm4t(u32& r0, u32& r1, u32& r2, u32& r3, u32 addr) {
    asm volatile("ldmatrix.sync.aligned.m8n8.x4.trans.shared.b16 {%0,%1,%2,%3}, [%4];"
                 : "=r"(r0), "=r"(r1), "=r"(r2), "=r"(r3) : "r"(addr));
}

__device__ __forceinline__ void cp16(u32 dst, const void* src) {
    asm volatile("cp.async.ca.shared.global [%0], [%1], 16;" :: "r"(dst), "l"(src));
}
__device__ __forceinline__ void cp_commit() { asm volatile("cp.async.commit_group;"); }
__device__ __forceinline__ void cp_wait0() { asm volatile("cp.async.wait_group 0;" ::: "memory"); }

// ---------------- spectral norm (templated, latency-parallel) ----------------
__device__ __forceinline__ float block_reduce_sum_128(float v, float* sred) {
    int t = threadIdx.x;
    sred[t] = v;
    __syncthreads();
    #pragma unroll
    for (int s = 64; s > 0; s >>= 1) {
        if (t < s) sred[t] += sred[t + s];
        __syncthreads();
    }
    float r = sred[0];
    __syncthreads();
    return r;
}

template <int O, int I>
__device__ __forceinline__ void sn_dev(const float* __restrict__ W,
                                       const float* __restrict__ u,
                                       float* __restrict__ Wn,
                                       float* su, float* sv, float* sred) {
    int t = threadIdx.x;
    // preload u into shared
    if (t < O) su[t] = u[t];
    __syncthreads();
    // v_raw = u @ W  (len I)
    float vr = 0.f;
    if (t < I) {
        #pragma unroll 16
        for (int o = 0; o < O; o++) vr += su[o] * W[o * I + t];
    }
    float nv2 = block_reduce_sum_128((t < I) ? vr * vr : 0.f, sred);
    float inv = 1.f / fmaxf(sqrtf(nv2), 1e-12f);
    if (t < I) sv[t] = vr * inv;
    __syncthreads();
    // u2_raw = v @ W^T (len O)
    float ur = 0.f;
    if (t < O) {
        #pragma unroll 16
        for (int i = 0; i < I; i++) ur += sv[i] * W[t * I + i];
    }
    float nu2 = block_reduce_sum_128((t < O) ? ur * ur : 0.f, sred);
    float invu = 1.f / fmaxf(sqrtf(nu2), 1e-12f);
    float sigma = block_reduce_sum_128((t < O) ? ur * ur * invu : 0.f, sred);
    float ws = 1.f / sigma;
    #pragma unroll
    for (int k = t; k < O * I / 4; k += 128) {
        float4 wv = ((const float4*)W)[k];
        ((float4*)Wn)[k] = make_float4(wv.x * ws, wv.y * ws, wv.z * ws, wv.w * ws);
    }
}

__global__ void sn_kernel(const float* w_theta, const float* w_phi,
                          const float* w_g, const float* w_o,
                          const float* u_theta, const float* u_phi,
                          const float* u_g, const float* u_o) {
    __shared__ float su[128];
    __shared__ float sv[128];
    __shared__ float sred[128];
    switch (blockIdx.x) {
        case 0:  sn_dev<CQ, CH>(w_theta, u_theta, g_Wt, su, sv, sred); break;
        case 1:  sn_dev<CQ, CH>(w_phi,   u_phi,   g_Wp, su, sv, sred); break;
        case 2:  sn_dev<CV, CH>(w_g,     u_g,     g_Wg, su, sv, sred); break;
        default: sn_dev<CH, CV>(w_o,     u_o,     g_Wo, su, sv, sred); break;
    }
}

// ---------------- fused input conv (theta | phi | g) via fp16 mma ----------------
#define XROW 272
#define SM_X 0
#define SM_W (128 * XROW)
#define CONV_SMEM (SM_W + 96 * XROW)

__global__ __launch_bounds__(256) void fusedconv_kernel(const float* __restrict__ x) {
    extern __shared__ char smc[];
    const u32 sXu = smem_u32(smc) + SM_X;
    const u32 sWu = smem_u32(smc) + SM_W;
    const int tid = threadIdx.x;
    const int w = tid >> 5, lane = tid & 31;
    const int b = blockIdx.x >> 5, j = blockIdx.x & 31;
    const int s0 = j * 128;

    for (int i = tid; i < 96 * 16; i += 256) {
        int out = i >> 4, seg = i & 15;
        const float* src;
        if (out < 16)      src = g_Wt + out * CH + seg * 8;
        else if (out < 32) src = g_Wp + (out - 16) * CH + seg * 8;
        else               src = g_Wg + (out - 32) * CH + seg * 8;
        float4 f0 = *(const float4*)src;
        float4 f1 = *(const float4*)(src + 4);
        uint4 v = make_uint4(h2u(f0.x, f0.y), h2u(f0.z, f0.w),
                             h2u(f1.x, f1.y), h2u(f1.z, f1.w));
        asm volatile("st.shared.v4.b32 [%0], {%1,%2,%3,%4};"
                     :: "r"(sWu + (u32)(out * XROW + seg * 16)),
                        "r"(v.x), "r"(v.y), "r"(v.z), "r"(v.w) : "memory");
    }
    for (int i = tid; i < 128 * 32; i += 256) {
        int ch = i >> 5, seg = i & 31;
        float4 f = *(const float4*)&x[((size_t)b * CH + ch) * HW + s0 + seg * 4];
        u32 h0 = h2u(f.x, f.y), h1 = h2u(f.z, f.w);
        asm volatile("st.shared.v2.b32 [%0], {%1,%2};"
                     :: "r"(sXu + (u32)(ch * XROW + seg * 8)), "r"(h0), "r"(h1) : "memory");
    }
    __syncthreads();

    const int jj = lane & 7, grp = lane >> 3;
    const u32 aBase = sXu + (u32)((((grp & 2) ? 8 : 0) + jj) * XROW
                                  + (16 * w + ((grp & 1) ? 8 : 0)) * 2);
    u32 bBase[6];
    #pragma unroll
    for (int np = 0; np < 6; np++)
        bBase[np] = sWu + (u32)((np * 16 + ((grp >> 1) ? 8 : 0) + jj) * XROW
                                + ((grp & 1) ? 16 : 0));

    float c[12][4];
    #pragma unroll
    for (int nt = 0; nt < 12; nt++)
        c[nt][0] = c[nt][1] = c[nt][2] = c[nt][3] = 0.f;

    #pragma unroll
    for (int t = 0; t < 8; t++) {
        u32 a[4];
        ldm4t(a[0], a[1], a[2], a[3], aBase + (u32)(t * 16 * XROW));
        #pragma unroll
        for (int np = 0; np < 6; np++) {
            u32 b0, b1, b2, b3;
            ldm4(b0, b1, b2, b3, bBase[np] + (u32)(t * 32));
            mmaf16(c[2 * np],     a, b0, b1);
            mmaf16(c[2 * np + 1], a, b2, b3);
        }
    }
    __syncthreads();

    const int g = lane >> 2, l = lane & 3;
    const int pxA = 16 * w + g;
    #pragma unroll
    for (int nt = 0; nt < 12; nt++) {
        u32 lo = h2u(c[nt][0], c[nt][1]);
        u32 hi = h2u(c[nt][2], c[nt][3]);
        asm volatile("st.shared.b32 [%0], %1;"
                     :: "r"(sXu + (u32)((pxA * 104 + nt * 8 + 2 * l) * 2)), "r"(lo) : "memory");
        asm volatile("st.shared.b32 [%0], %1;"
                     :: "r"(sXu + (u32)(((pxA + 8) * 104 + nt * 8 + 2 * l) * 2)), "r"(hi) : "memory");
    }
    __syncthreads();

    const __half* sCh = (const __half*)smc;
    {
        int px = tid >> 1, h = tid & 1;
        uint4 v = *(const uint4*)(sCh + px * 104 + h * 8);
        *(uint4*)&d_theta_h[((size_t)b * HW + s0 + px) * CQ + h * 8] = v;
    }
    if (tid < 64) {
        int wp = tid >> 1, h = tid & 1;
        int off = 16 + h * 8;
        const __half2* p0 = (const __half2*)(sCh + (2 * wp) * 104 + off);
        const __half2* p1 = (const __half2*)(sCh + (2 * wp + 1) * 104 + off);
        const __half2* p2 = (const __half2*)(sCh + (64 + 2 * wp) * 104 + off);
        const __half2* p3 = (const __half2*)(sCh + (65 + 2 * wp) * 104 + off);
        __half2 r[4];
        #pragma unroll
        for (int k = 0; k < 4; k++)
            r[k] = __hmax2(__hmax2(p0[k], p1[k]), __hmax2(p2[k], p3[k]));
        *(uint4*)&d_phi_h[((size_t)b * TT + j * 32 + wp) * CQ + h * 8] = *(uint4*)r;
    }
    if (tid < 128) {
        int ch = tid >> 1, wh = (tid & 1) * 16;
        __half2 outv[8];
        #pragma unroll
        for (int k2 = 0; k2 < 8; k2++) {
            __half v[2];
            #pragma unroll
            for (int u = 0; u < 2; u++) {
                int wp = wh + k2 * 2 + u;
                __half a0 = sCh[(2 * wp) * 104 + 32 + ch];
                __half a1 = sCh[(2 * wp + 1) * 104 + 32 + ch];
                __half a2 = sCh[(64 + 2 * wp) * 104 + 32 + ch];
                __half a3 = sCh[(65 + 2 * wp) * 104 + 32 + ch];
                v[u] = __hmax(__hmax(a0, a1), __hmax(a2, a3));
            }
            outv[k2] = __halves2half2(v[0], v[1]);
        }
        __half* dst = &d_gT_h[((size_t)b * CV + ch) * TT + j * 32 + wh];
        #pragma unroll
        for (int k2 = 0; k2 < 8; k2++) ((__half2*)dst)[k2] = outv[k2];
    }
}

// ---- attention + fused output conv + residual --------------------------------
#define KSW 8
#define VSW 36
#define KSTG (64 * KSW)
#define VSTG (64 * VSW)
#define OROWB 144
#define ATTN_SMEM_BYTES (2 * KSTG * 4 + 2 * VSTG * 4 + 128 * OROWB)  // 40960

__global__ __launch_bounds__(256, 2) void attn_fused_kernel(const float* __restrict__ x,
                                                            const float* __restrict__ gptr,
                                                            float* __restrict__ out) {
    __shared__ __align__(16) char sbuf[ATTN_SMEM_BYTES];
    u32* sK = (u32*)sbuf;
    u32* sV = sK + 2 * KSTG;
    const u32 kbase = smem_u32(sbuf);
    const u32 vbase = kbase + 2 * KSTG * 4;
    const u32 wobase = kbase + 2 * KSTG * 4 + 2 * VSTG * 4;
    float* sB = (float*)sbuf;   // bounce, overlays sK+sV after mainloop

    const int tid = threadIdx.x;
    const int w = tid >> 5, lane = tid & 31;
    const int g = lane >> 2, l = lane & 3;
    const int qbase = blockIdx.x * 128 + w * 16;
    const int b = (int)((blockIdx.x * 128) >> 12);
    const int s0 = (blockIdx.x * 128) & 4095;
    const __half* phib = &d_phi_h[(size_t)(b << 10) * CQ];
    const __half* gTb  = &d_gT_h[(size_t)b * CV * TT];

    // fill Wo smem: [128 out][64 k] f32 -> fp16, row stride 144B
    for (int i = tid; i < 128 * 8; i += 256) {
        int o8 = i >> 3, seg = i & 7;
        const float* src = g_Wo + o8 * CV + seg * 8;
        float4 f0 = *(const float4*)src;
        float4 f1 = *(const float4*)(src + 4);
        uint4 v = make_uint4(h2u(f0.x, f0.y), h2u(f0.z, f0.w),
                             h2u(f1.x, f1.y), h2u(f1.z, f1.w));
        asm volatile("st.shared.v4.b32 [%0], {%1,%2,%3,%4};"
                     :: "r"(wobase + (u32)(o8 * OROWB + seg * 16)),
                        "r"(v.x), "r"(v.y), "r"(v.z), "r"(v.w) : "memory");
    }

    u32 qh[4];
    {
        const u32* q0 = (const u32*)&d_theta_h[(size_t)(qbase + g) * CQ];
        const u32* q1 = (const u32*)&d_theta_h[(size_t)(qbase + g + 8) * CQ];
        qh[0] = q0[l];     qh[1] = q1[l];
        qh[2] = q0[l + 4]; qh[3] = q1[l + 4];
    }

    float o[8][4];
    #pragma unroll
    for (int nt = 0; nt < 8; nt++)
        #pragma unroll
        for (int jj = 0; jj < 4; jj++) o[nt][jj] = 0.f;
    float mA = NEG_INF, mB = NEG_INF, lA = 0.f, lB = 0.f;

    auto fill = [&](int stage, int c0) {
        if (tid < 128) {
            int row = tid >> 1, part = tid & 1;
            cp16(kbase + (u32)((stage * KSTG + row * KSW + part * 4) * 4),
                 phib + (c0 + row) * CQ + part * 8);
        }
        #pragma unroll
        for (int i = 0; i < 2; i++) {
            int idx = tid * 2 + i;
            int c = idx >> 3, t8 = idx & 7;
            cp16(vbase + (u32)((stage * VSTG + c * VSW + t8 * 4) * 4),
                 gTb + (size_t)c * TT + c0 + t8 * 8);
        }
        cp_commit();
    };

    fill(0, 0);
    cp_wait0();
    __syncthreads();

    for (int c0 = 0; c0 < TT; c0 += 64) {
        int stage = (c0 >> 6) & 1;
        const u32* cK = sK + stage * KSTG;
        const u32* cV = sV + stage * VSTG;

        if (c0 + 64 < TT) fill(stage ^ 1, c0 + 64);

        float c[8][4];
        #pragma unroll
        for (int nt = 0; nt < 8; nt++) {
            c[nt][0] = c[nt][1] = c[nt][2] = c[nt][3] = 0.f;
            int kr = (nt * 8 + g) * KSW;
            mmaf16(c[nt], qh, cK[kr + l], cK[kr + l + 4]);
        }

        float cmA = NEG_INF, cmB = NEG_INF;
        #pragma unroll
        for (int nt = 0; nt < 8; nt++) {
            cmA = fmaxf(cmA, fmaxf(c[nt][0], c[nt][1]));
            cmB = fmaxf(cmB, fmaxf(c[nt][2], c[nt][3]));
        }
        cmA = fmaxf(cmA, __shfl_xor_sync(0xffffffffu, cmA, 1));
        cmA = fmaxf(cmA, __shfl_xor_sync(0xffffffffu, cmA, 2));
        cmB = fmaxf(cmB, __shfl_xor_sync(0xffffffffu, cmB, 1));
        cmB = fmaxf(cmB, __shfl_xor_sync(0xffffffffu, cmB, 2));
        float nmA = fmaxf(mA, cmA), nmB = fmaxf(mB, cmB);
        float sA = __expf(mA - nmA), sB2 = __expf(mB - nmB);
        mA = nmA; mB = nmB;
        lA *= sA; lB *= sB2;

        u32 pa[4][4];
        #pragma unroll
        for (int nt = 0; nt < 8; nt++) {
            o[nt][0] *= sA; o[nt][1] *= sA; o[nt][2] *= sB2; o[nt][3] *= sB2;
            float p0 = __expf(c[nt][0] - mA);
            float p1 = __expf(c[nt][1] - mA);
            float p2 = __expf(c[nt][2] - mB);
            float p3 = __expf(c[nt][3] - mB);
            lA += p0 + p1; lB += p2 + p3;
            int kb = nt >> 1, hi = nt & 1;
            pa[kb][hi * 2]     = h2u(p0, p1);
            pa[kb][hi * 2 + 1] = h2u(p2, p3);
        }

        #pragma unroll
        for (int kb = 0; kb < 4; kb++) {
            #pragma unroll
            for (int nt = 0; nt < 8; nt++) {
                int vr = (nt * 8 + g) * VSW + kb * 8 + l;
                mmaf16(o[nt], pa[kb], cV[vr], cV[vr + 4]);
            }
        }

        cp_wait0();
        __syncthreads();
    }

    // ---- normalize o, build fp16 A-fragments ----
    lA += __shfl_xor_sync(0xffffffffu, lA, 1);
    lA += __shfl_xor_sync(0xffffffffu, lA, 2);
    lB += __shfl_xor_sync(0xffffffffu, lB, 1);
    lB += __shfl_xor_sync(0xffffffffu, lB, 2);
    float iA = 1.f / lA, iB = 1.f / lB;
    u32 a2[4][4];
    #pragma unroll
    for (int kb = 0; kb < 4; kb++) {
        a2[kb][0] = h2u(o[2*kb][0] * iA,     o[2*kb][1] * iA);
        a2[kb][1] = h2u(o[2*kb][2] * iB,     o[2*kb][3] * iB);
        a2[kb][2] = h2u(o[2*kb + 1][0] * iA, o[2*kb + 1][1] * iA);
        a2[kb][3] = h2u(o[2*kb + 1][2] * iB, o[2*kb + 1][3] * iB);
    }

    // ---- fused output conv: out = gamma * (o_norm @ Wo^T) + x ----
    const float gamma = *gptr;
    const int jj = lane & 7, grp = lane >> 3;
    #pragma unroll
    for (int pp = 0; pp < 4; pp++) {       // 32-out-channel groups
        float c2[4][4];
        #pragma unroll
        for (int nt = 0; nt < 4; nt++)
            c2[nt][0] = c2[nt][1] = c2[nt][2] = c2[nt][3] = 0.f;
        #pragma unroll
        for (int t = 0; t < 4; t++) {
            #pragma unroll
            for (int np = 0; np < 2; np++) {
                u32 b0, b1, b2, b3;
                u32 baddr = wobase + (u32)((pp * 32 + np * 16 + ((grp >> 1) ? 8 : 0) + jj) * OROWB
                                           + ((grp & 1) ? 16 : 0) + t * 32);
                ldm4(b0, b1, b2, b3, baddr);
                mmaf16(c2[2 * np],     a2[t], b0, b1);
                mmaf16(c2[2 * np + 1], a2[t], b2, b3);
            }
        }
        // bounce [32 ch][132] f32
        #pragma unroll
        for (int nt = 0; nt < 4; nt++) {
            int cl = (nt >> 1) * 16 + (nt & 1) * 8 + 2 * l;
            sB[cl * 132 + 16 * w + g]           = c2[nt][0];
            sB[(cl + 1) * 132 + 16 * w + g]     = c2[nt][1];
            sB[cl * 132 + 16 * w + g + 8]       = c2[nt][2];
            sB[(cl + 1) * 132 + 16 * w + g + 8] = c2[nt][3];
        }
        __syncthreads();
        // coalesced write: 32 ch x 128 px = 1024 float4
        #pragma unroll
        for (int k = 0; k < 4; k++) {
            int flat = k * 256 + tid;
            int cc = flat >> 5, pxg = flat & 31;
            float4 v = *(const float4*)&sB[cc * 132 + pxg * 4];
            size_t idx = ((size_t)(b * CH) + pp * 32 + cc) * HW + s0 + pxg * 4;
            float4 xv = *(const float4*)&x[idx];
            *(float4*)&out[idx] = make_float4(gamma * v.x + xv.x, gamma * v.y + xv.y,
                                              gamma * v.z + xv.z, gamma * v.w + xv.w);
        }
        __syncthreads();
    }
}

// ---------------- launch ----------------
extern "C" void kernel_launch(void* const* d_in, const int* in_sizes, int n_in,
                              void* d_out, int out_size) {
    const float* x       = (const float*)d_in[0];
    const float* w_theta = (const float*)d_in[1];
    const float* w_phi   = (const float*)d_in[2];
    const float* w_g     = (const float*)d_in[3];
    const float* w_o     = (const float*)d_in[4];
    const float* u_theta = (const float*)d_in[5];
    const float* u_phi   = (const float*)d_in[6];
    const float* u_g     = (const float*)d_in[7];
    const float* u_o     = (const float*)d_in[8];
    const float* gamma   = (const float*)d_in[9];
    float* out = (float*)d_out;

    cudaFuncSetAttribute(fusedconv_kernel, cudaFuncAttributeMaxDynamicSharedMemorySize, CONV_SMEM);

    sn_kernel<<<4, 128>>>(w_theta, w_phi, w_g, w_o, u_theta, u_phi, u_g, u_o);
    fusedconv_kernel<<<512, 256, CONV_SMEM>>>(x);
    attn_fused_kernel<<<512, 256>>>(x, gamma, out);
}

// round 14
// speedup vs baseline: 1.2867x; 1.0409x over previous
#include <cuda_runtime.h>
#include <cuda_fp16.h>
#include <cstdint>

#define BATCH 16
#define CH    128
#define HH    64
#define WW    64
#define HW    4096
#define CQ    16
#define CV    64
#define TT    1024
#define NEG_INF (-3.402823466e38f)

typedef unsigned long long ull;
typedef unsigned int u32;

// ---------------- scratch ----------------
__device__ float g_Wt[CQ * CH];
__device__ float g_Wp[CQ * CH];
__device__ float g_Wg[CV * CH];
__device__ float g_Wo[CH * CV];

__device__ __half d_theta_h[BATCH * HW * CQ];  // [b][s][16] fp16
__device__ __half d_phi_h[BATCH * TT * CQ];    // [b][t][16] fp16
__device__ __half d_gT_h[BATCH * CV * TT];     // [b][c][t]  fp16 transposed

// ---------------- helpers ----------------
__device__ __forceinline__ u32 h2u(float a, float b) {
    __half2 h = __floats2half2_rn(a, b);
    return *reinterpret_cast<u32*>(&h);
}
__device__ __forceinline__ u32 smem_u32(const void* p) {
    u32 a;
    asm("{ .reg .u64 t; cvta.to.shared.u64 t, %1; cvt.u32.u64 %0, t; }" : "=r"(a) : "l"(p));
    return a;
}

// fp16 mma m16n8k16, f32 accumulate
__device__ __forceinline__ void mmaf16(float c[4], const u32 a[4], u32 b0, u32 b1) {
    asm("mma.sync.aligned.m16n8k16.row.col.f32.f16.f16.f32 "
        "{%0,%1,%2,%3}, {%4,%5,%6,%7}, {%8,%9}, {%0,%1,%2,%3};"
        : "+f"(c[0]), "+f"(c[1]), "+f"(c[2]), "+f"(c[3])
        : "r"(a[0]), "r"(a[1]), "r"(a[2]), "r"(a[3]), "r"(b0), "r"(b1));
}
__device__ __forceinline__ void ldm4(u32& r0, u32& r1, u32& r2, u32& r3, u32 addr) {
    asm volatile("ldmatrix.sync.aligned.m8n8.x4.shared.b16 {%0,%1,%2,%3}, [%4];"
                 : "=r"(r0), "=r"(r1), "=r"(r2), "=r"(r3) : "r"(addr));
}
__device__ __forceinline__ void ldm4t(u32& r0, u32& r1, u32& r2, u32& r3, u32 addr) {
    asm volatile("ldmatrix.sync.aligned.m8n8.x4.trans.shared.b16 {%0,%1,%2,%3}, [%4];"
                 : "=r"(r0), "=r"(r1), "=r"(r2), "=r"(r3) : "r"(addr));
}

__device__ __forceinline__ void cp16(u32 dst, const void* src) {
    asm volatile("cp.async.ca.shared.global [%0], [%1], 16;" :: "r"(dst), "l"(src));
}
__device__ __forceinline__ void cp_commit() { asm volatile("cp.async.commit_group;"); }
__device__ __forceinline__ void cp_wait0() { asm volatile("cp.async.wait_group 0;" ::: "memory"); }

// ---------------- spectral norm (smem-staged, latency-parallel) ----------------
__device__ __forceinline__ float block_sum_128(float v, float* sred) {
    int lane = threadIdx.x & 31, w = threadIdx.x >> 5;
    v += __shfl_xor_sync(0xffffffffu, v, 16);
    v += __shfl_xor_sync(0xffffffffu, v, 8);
    v += __shfl_xor_sync(0xffffffffu, v, 4);
    v += __shfl_xor_sync(0xffffffffu, v, 2);
    v += __shfl_xor_sync(0xffffffffu, v, 1);
    if (lane == 0) sred[w] = v;
    __syncthreads();
    float r = sred[0] + sred[1] + sred[2] + sred[3];
    __syncthreads();
    return r;
}

template <int O, int I>
__device__ __forceinline__ void sn_dev(const float* __restrict__ W,
                                       const float* __restrict__ u,
                                       float* __restrict__ Wn,
                                       float* sW, float* su, float* sv, float* sred) {
    const int t = threadIdx.x;
    const int S = I + 5;   // row stride: (I+5) mod 32 = 5, gcd(5,32)=1 -> both phases conflict-free
    if (t < O) su[t] = u[t];
    // stage W into smem: coalesced float4 loads, MLP = (O*I/4)/128
    #pragma unroll
    for (int k4 = t; k4 < O * I / 4; k4 += 128) {
        int row = k4 / (I / 4), c4 = k4 % (I / 4);
        float4 wv = ((const float4*)W)[k4];
        float* dst = &sW[row * S + c4 * 4];
        dst[0] = wv.x; dst[1] = wv.y; dst[2] = wv.z; dst[3] = wv.w;
    }
    __syncthreads();
    // v_raw = u @ W  (len I)
    float vr = 0.f;
    if (t < I) {
        #pragma unroll
        for (int o = 0; o < O; o++) vr += su[o] * sW[o * S + t];
    }
    float nv2 = block_sum_128((t < I) ? vr * vr : 0.f, sred);
    float inv = 1.f / fmaxf(sqrtf(nv2), 1e-12f);
    if (t < I) sv[t] = vr * inv;
    __syncthreads();
    // u2_raw = v @ W^T (len O)
    float ur = 0.f;
    if (t < O) {
        #pragma unroll
        for (int i = 0; i < I; i++) ur += sv[i] * sW[t * S + i];
    }
    float nu2 = block_sum_128((t < O) ? ur * ur : 0.f, sred);
    float invu = 1.f / fmaxf(sqrtf(nu2), 1e-12f);
    float sigma = block_sum_128((t < O) ? ur * ur * invu : 0.f, sred);
    float ws = 1.f / sigma;
    #pragma unroll
    for (int k = t; k < O * I / 4; k += 128) {
        float4 wv = ((const float4*)W)[k];   // L1/L2-hot after staging
        ((float4*)Wn)[k] = make_float4(wv.x * ws, wv.y * ws, wv.z * ws, wv.w * ws);
    }
}

__global__ void sn_kernel(const float* w_theta, const float* w_phi,
                          const float* w_g, const float* w_o,
                          const float* u_theta, const float* u_phi,
                          const float* u_g, const float* u_o) {
    __shared__ float sW[8832];   // max(O*(I+5)) = 128*69 = 8832 floats = 34.5 KB
    __shared__ float su[128];
    __shared__ float sv[128];
    __shared__ float sred[4];
    switch (blockIdx.x) {
        case 0:  sn_dev<CQ, CH>(w_theta, u_theta, g_Wt, sW, su, sv, sred); break;
        case 1:  sn_dev<CQ, CH>(w_phi,   u_phi,   g_Wp, sW, su, sv, sred); break;
        case 2:  sn_dev<CV, CH>(w_g,     u_g,     g_Wg, sW, su, sv, sred); break;
        default: sn_dev<CH, CV>(w_o,     u_o,     g_Wo, sW, su, sv, sred); break;
    }
}

// ---------------- fused input conv (theta | phi | g) via fp16 mma ----------------
#define XROW 272
#define SM_X 0
#define SM_W (128 * XROW)
#define CONV_SMEM (SM_W + 96 * XROW)

__global__ __launch_bounds__(256) void fusedconv_kernel(const float* __restrict__ x) {
    extern __shared__ char smc[];
    const u32 sXu = smem_u32(smc) + SM_X;
    const u32 sWu = smem_u32(smc) + SM_W;
    const int tid = threadIdx.x;
    const int w = tid >> 5, lane = tid & 31;
    const int b = blockIdx.x >> 5, j = blockIdx.x & 31;
    const int s0 = j * 128;

    for (int i = tid; i < 96 * 16; i += 256) {
        int out = i >> 4, seg = i & 15;
        const float* src;
        if (out < 16)      src = g_Wt + out * CH + seg * 8;
        else if (out < 32) src = g_Wp + (out - 16) * CH + seg * 8;
        else               src = g_Wg + (out - 32) * CH + seg * 8;
        float4 f0 = *(const float4*)src;
        float4 f1 = *(const float4*)(src + 4);
        uint4 v = make_uint4(h2u(f0.x, f0.y), h2u(f0.z, f0.w),
                             h2u(f1.x, f1.y), h2u(f1.z, f1.w));
        asm volatile("st.shared.v4.b32 [%0], {%1,%2,%3,%4};"
                     :: "r"(sWu + (u32)(out * XROW + seg * 16)),
                        "r"(v.x), "r"(v.y), "r"(v.z), "r"(v.w) : "memory");
    }
    for (int i = tid; i < 128 * 32; i += 256) {
        int ch = i >> 5, seg = i & 31;
        float4 f = *(const float4*)&x[((size_t)b * CH + ch) * HW + s0 + seg * 4];
        u32 h0 = h2u(f.x, f.y), h1 = h2u(f.z, f.w);
        asm volatile("st.shared.v2.b32 [%0], {%1,%2};"
                     :: "r"(sXu + (u32)(ch * XROW + seg * 8)), "r"(h0), "r"(h1) : "memory");
    }
    __syncthreads();

    const int jj = lane & 7, grp = lane >> 3;
    const u32 aBase = sXu + (u32)((((grp & 2) ? 8 : 0) + jj) * XROW
                                  + (16 * w + ((grp & 1) ? 8 : 0)) * 2);
    u32 bBase[6];
    #pragma unroll
    for (int np = 0; np < 6; np++)
        bBase[np] = sWu + (u32)((np * 16 + ((grp >> 1) ? 8 : 0) + jj) * XROW
                                + ((grp & 1) ? 16 : 0));

    float c[12][4];
    #pragma unroll
    for (int nt = 0; nt < 12; nt++)
        c[nt][0] = c[nt][1] = c[nt][2] = c[nt][3] = 0.f;

    #pragma unroll
    for (int t = 0; t < 8; t++) {
        u32 a[4];
        ldm4t(a[0], a[1], a[2], a[3], aBase + (u32)(t * 16 * XROW));
        #pragma unroll
        for (int np = 0; np < 6; np++) {
            u32 b0, b1, b2, b3;
            ldm4(b0, b1, b2, b3, bBase[np] + (u32)(t * 32));
            mmaf16(c[2 * np],     a, b0, b1);
            mmaf16(c[2 * np + 1], a, b2, b3);
        }
    }
    __syncthreads();

    const int g = lane >> 2, l = lane & 3;
    const int pxA = 16 * w + g;
    #pragma unroll
    for (int nt = 0; nt < 12; nt++) {
        u32 lo = h2u(c[nt][0], c[nt][1]);
        u32 hi = h2u(c[nt][2], c[nt][3]);
        asm volatile("st.shared.b32 [%0], %1;"
                     :: "r"(sXu + (u32)((pxA * 104 + nt * 8 + 2 * l) * 2)), "r"(lo) : "memory");
        asm volatile("st.shared.b32 [%0], %1;"
                     :: "r"(sXu + (u32)(((pxA + 8) * 104 + nt * 8 + 2 * l) * 2)), "r"(hi) : "memory");
    }
    __syncthreads();

    const __half* sCh = (const __half*)smc;
    {
        int px = tid >> 1, h = tid & 1;
        uint4 v = *(const uint4*)(sCh + px * 104 + h * 8);
        *(uint4*)&d_theta_h[((size_t)b * HW + s0 + px) * CQ + h * 8] = v;
    }
    if (tid < 64) {
        int wp = tid >> 1, h = tid & 1;
        int off = 16 + h * 8;
        const __half2* p0 = (const __half2*)(sCh + (2 * wp) * 104 + off);
        const __half2* p1 = (const __half2*)(sCh + (2 * wp + 1) * 104 + off);
        const __half2* p2 = (const __half2*)(sCh + (64 + 2 * wp) * 104 + off);
        const __half2* p3 = (const __half2*)(sCh + (65 + 2 * wp) * 104 + off);
        __half2 r[4];
        #pragma unroll
        for (int k = 0; k < 4; k++)
            r[k] = __hmax2(__hmax2(p0[k], p1[k]), __hmax2(p2[k], p3[k]));
        *(uint4*)&d_phi_h[((size_t)b * TT + j * 32 + wp) * CQ + h * 8] = *(uint4*)r;
    }
    if (tid < 128) {
        int ch = tid >> 1, wh = (tid & 1) * 16;
        __half2 outv[8];
        #pragma unroll
        for (int k2 = 0; k2 < 8; k2++) {
            __half v[2];
            #pragma unroll
            for (int u = 0; u < 2; u++) {
                int wp = wh + k2 * 2 + u;
                __half a0 = sCh[(2 * wp) * 104 + 32 + ch];
                __half a1 = sCh[(2 * wp + 1) * 104 + 32 + ch];
                __half a2 = sCh[(64 + 2 * wp) * 104 + 32 + ch];
                __half a3 = sCh[(65 + 2 * wp) * 104 + 32 + ch];
                v[u] = __hmax(__hmax(a0, a1), __hmax(a2, a3));
            }
            outv[k2] = __halves2half2(v[0], v[1]);
        }
        __half* dst = &d_gT_h[((size_t)b * CV + ch) * TT + j * 32 + wh];
        #pragma unroll
        for (int k2 = 0; k2 < 8; k2++) ((__half2*)dst)[k2] = outv[k2];
    }
}

// ---- attention + fused output conv + residual --------------------------------
#define KSW 8
#define VSW 36
#define KSTG (64 * KSW)
#define VSTG (64 * VSW)
#define OROWB 144
#define ATTN_SMEM_BYTES (2 * KSTG * 4 + 2 * VSTG * 4 + 128 * OROWB)  // 40960

__global__ __launch_bounds__(256, 2) void attn_fused_kernel(const float* __restrict__ x,
                                                            const float* __restrict__ gptr,
                                                            float* __restrict__ out) {
    __shared__ __align__(16) char sbuf[ATTN_SMEM_BYTES];
    u32* sK = (u32*)sbuf;
    u32* sV = sK + 2 * KSTG;
    const u32 kbase = smem_u32(sbuf);
    const u32 vbase = kbase + 2 * KSTG * 4;
    const u32 wobase = kbase + 2 * KSTG * 4 + 2 * VSTG * 4;
    float* sB = (float*)sbuf;   // bounce, overlays sK+sV after mainloop

    const int tid = threadIdx.x;
    const int w = tid >> 5, lane = tid & 31;
    const int g = lane >> 2, l = lane & 3;
    const int qbase = blockIdx.x * 128 + w * 16;
    const int b = (int)((blockIdx.x * 128) >> 12);
    const int s0 = (blockIdx.x * 128) & 4095;
    const __half* phib = &d_phi_h[(size_t)(b << 10) * CQ];
    const __half* gTb  = &d_gT_h[(size_t)b * CV * TT];

    // fill Wo smem: [128 out][64 k] f32 -> fp16, row stride 144B
    for (int i = tid; i < 128 * 8; i += 256) {
        int o8 = i >> 3, seg = i & 7;
        const float* src = g_Wo + o8 * CV + seg * 8;
        float4 f0 = *(const float4*)src;
        float4 f1 = *(const float4*)(src + 4);
        uint4 v = make_uint4(h2u(f0.x, f0.y), h2u(f0.z, f0.w),
                             h2u(f1.x, f1.y), h2u(f1.z, f1.w));
        asm volatile("st.shared.v4.b32 [%0], {%1,%2,%3,%4};"
                     :: "r"(wobase + (u32)(o8 * OROWB + seg * 16)),
                        "r"(v.x), "r"(v.y), "r"(v.z), "r"(v.w) : "memory");
    }

    u32 qh[4];
    {
        const u32* q0 = (const u32*)&d_theta_h[(size_t)(qbase + g) * CQ];
        const u32* q1 = (const u32*)&d_theta_h[(size_t)(qbase + g + 8) * CQ];
        qh[0] = q0[l];     qh[1] = q1[l];
        qh[2] = q0[l + 4]; qh[3] = q1[l + 4];
    }

    float o[8][4];
    #pragma unroll
    for (int nt = 0; nt < 8; nt++)
        #pragma unroll
        for (int jj = 0; jj < 4; jj++) o[nt][jj] = 0.f;
    float mA = NEG_INF, mB = NEG_INF, lA = 0.f, lB = 0.f;

    auto fill = [&](int stage, int c0) {
        if (tid < 128) {
            int row = tid >> 1, part = tid & 1;
            cp16(kbase + (u32)((stage * KSTG + row * KSW + part * 4) * 4),
                 phib + (c0 + row) * CQ + part * 8);
        }
        #pragma unroll
        for (int i = 0; i < 2; i++) {
            int idx = tid * 2 + i;
            int c = idx >> 3, t8 = idx & 7;
            cp16(vbase + (u32)((stage * VSTG + c * VSW + t8 * 4) * 4),
                 gTb + (size_t)c * TT + c0 + t8 * 8);
        }
        cp_commit();
    };

    fill(0, 0);
    cp_wait0();
    __syncthreads();

    for (int c0 = 0; c0 < TT; c0 += 64) {
        int stage = (c0 >> 6) & 1;
        const u32* cK = sK + stage * KSTG;
        const u32* cV = sV + stage * VSTG;

        if (c0 + 64 < TT) fill(stage ^ 1, c0 + 64);

        float c[8][4];
        #pragma unroll
        for (int nt = 0; nt < 8; nt++) {
            c[nt][0] = c[nt][1] = c[nt][2] = c[nt][3] = 0.f;
            int kr = (nt * 8 + g) * KSW;
            mmaf16(c[nt], qh, cK[kr + l], cK[kr + l + 4]);
        }

        float cmA = NEG_INF, cmB = NEG_INF;
        #pragma unroll
        for (int nt = 0; nt < 8; nt++) {
            cmA = fmaxf(cmA, fmaxf(c[nt][0], c[nt][1]));
            cmB = fmaxf(cmB, fmaxf(c[nt][2], c[nt][3]));
        }
        cmA = fmaxf(cmA, __shfl_xor_sync(0xffffffffu, cmA, 1));
        cmA = fmaxf(cmA, __shfl_xor_sync(0xffffffffu, cmA, 2));
        cmB = fmaxf(cmB, __shfl_xor_sync(0xffffffffu, cmB, 1));
        cmB = fmaxf(cmB, __shfl_xor_sync(0xffffffffu, cmB, 2));
        float nmA = fmaxf(mA, cmA), nmB = fmaxf(mB, cmB);
        float sA = __expf(mA - nmA), sB2 = __expf(mB - nmB);
        mA = nmA; mB = nmB;
        lA *= sA; lB *= sB2;

        u32 pa[4][4];
        #pragma unroll
        for (int nt = 0; nt < 8; nt++) {
            o[nt][0] *= sA; o[nt][1] *= sA; o[nt][2] *= sB2; o[nt][3] *= sB2;
            float p0 = __expf(c[nt][0] - mA);
            float p1 = __expf(c[nt][1] - mA);
            float p2 = __expf(c[nt][2] - mB);
            float p3 = __expf(c[nt][3] - mB);
            lA += p0 + p1; lB += p2 + p3;
            int kb = nt >> 1, hi = nt & 1;
            pa[kb][hi * 2]     = h2u(p0, p1);
            pa[kb][hi * 2 + 1] = h2u(p2, p3);
        }

        #pragma unroll
        for (int kb = 0; kb < 4; kb++) {
            #pragma unroll
            for (int nt = 0; nt < 8; nt++) {
                int vr = (nt * 8 + g) * VSW + kb * 8 + l;
                mmaf16(o[nt], pa[kb], cV[vr], cV[vr + 4]);
            }
        }

        cp_wait0();
        __syncthreads();
    }

    // ---- normalize o, build fp16 A-fragments ----
    lA += __shfl_xor_sync(0xffffffffu, lA, 1);
    lA += __shfl_xor_sync(0xffffffffu, lA, 2);
    lB += __shfl_xor_sync(0xffffffffu, lB, 1);
    lB += __shfl_xor_sync(0xffffffffu, lB, 2);
    float iA = 1.f / lA, iB = 1.f / lB;
    u32 a2[4][4];
    #pragma unroll
    for (int kb = 0; kb < 4; kb++) {
        a2[kb][0] = h2u(o[2*kb][0] * iA,     o[2*kb][1] * iA);
        a2[kb][1] = h2u(o[2*kb][2] * iB,     o[2*kb][3] * iB);
        a2[kb][2] = h2u(o[2*kb + 1][0] * iA, o[2*kb + 1][1] * iA);
        a2[kb][3] = h2u(o[2*kb + 1][2] * iB, o[2*kb + 1][3] * iB);
    }

    // ---- fused output conv: out = gamma * (o_norm @ Wo^T) + x ----
    const float gamma = *gptr;
    const int jj = lane & 7, grp = lane >> 3;
    #pragma unroll
    for (int pp = 0; pp < 4; pp++) {       // 32-out-channel groups
        float c2[4][4];
        #pragma unroll
        for (int nt = 0; nt < 4; nt++)
            c2[nt][0] = c2[nt][1] = c2[nt][2] = c2[nt][3] = 0.f;
        #pragma unroll
        for (int t = 0; t < 4; t++) {
            #pragma unroll
            for (int np = 0; np < 2; np++) {
                u32 b0, b1, b2, b3;
                u32 baddr = wobase + (u32)((pp * 32 + np * 16 + ((grp >> 1) ? 8 : 0) + jj) * OROWB
                                           + ((grp & 1) ? 16 : 0) + t * 32);
                ldm4(b0, b1, b2, b3, baddr);
                mmaf16(c2[2 * np],     a2[t], b0, b1);
                mmaf16(c2[2 * np + 1], a2[t], b2, b3);
            }
        }
        // bounce [32 ch][132] f32
        #pragma unroll
        for (int nt = 0; nt < 4; nt++) {
            int cl = (nt >> 1) * 16 + (nt & 1) * 8 + 2 * l;
            sB[cl * 132 + 16 * w + g]           = c2[nt][0];
            sB[(cl + 1) * 132 + 16 * w + g]     = c2[nt][1];
            sB[cl * 132 + 16 * w + g + 8]       = c2[nt][2];
            sB[(cl + 1) * 132 + 16 * w + g + 8] = c2[nt][3];
        }
        __syncthreads();
        // coalesced write: 32 ch x 128 px = 1024 float4
        #pragma unroll
        for (int k = 0; k < 4; k++) {
            int flat = k * 256 + tid;
            int cc = flat >> 5, pxg = flat & 31;
            float4 v = *(const float4*)&sB[cc * 132 + pxg * 4];
            size_t idx = ((size_t)(b * CH) + pp * 32 + cc) * HW + s0 + pxg * 4;
            float4 xv = *(const float4*)&x[idx];
            *(float4*)&out[idx] = make_float4(gamma * v.x + xv.x, gamma * v.y + xv.y,
                                              gamma * v.z + xv.z, gamma * v.w + xv.w);
        }
        __syncthreads();
    }
}

// ---------------- launch ----------------
extern "C" void kernel_launch(void* const* d_in, const int* in_sizes, int n_in,
                              void* d_out, int out_size) {
    const float* x       = (const float*)d_in[0];
    const float* w_theta = (const float*)d_in[1];
    const float* w_phi   = (const float*)d_in[2];
    const float* w_g     = (const float*)d_in[3];
    const float* w_o     = (const float*)d_in[4];
    const float* u_theta = (const float*)d_in[5];
    const float* u_phi   = (const float*)d_in[6];
    const float* u_g     = (const float*)d_in[7];
    const float* u_o     = (const float*)d_in[8];
    const float* gamma   = (const float*)d_in[9];
    float* out = (float*)d_out;

    cudaFuncSetAttribute(fusedconv_kernel, cudaFuncAttributeMaxDynamicSharedMemorySize, CONV_SMEM);

    sn_kernel<<<4, 128>>>(w_theta, w_phi, w_g, w_o, u_theta, u_phi, u_g, u_o);
    fusedconv_kernel<<<512, 256, CONV_SMEM>>>(x);
    attn_fused_kernel<<<512, 256>>>(x, gamma, out);
}

// round 15
// speedup vs baseline: 1.4502x; 1.1270x over previous
#include <cuda_runtime.h>
#include <cuda_fp16.h>
#include <cstdint>

#define BATCH 16
#define CH    128
#define HH    64
#define WW    64
#define HW    4096
#define CQ    16
#define CV    64
#define TT    1024
#define NEG_INF (-3.402823466e38f)
#define LOG2E 1.4426950408889634f

typedef unsigned long long ull;
typedef unsigned int u32;

// ---------------- scratch ----------------
__device__ float g_sig[4];                     // sigma_theta, sigma_phi, sigma_g, sigma_o

__device__ __half d_theta_h[BATCH * HW * CQ];  // [b][s][16] fp16  (scaled by LOG2E/sig_t)
__device__ __half d_phi_h[BATCH * TT * CQ];    // [b][t][16] fp16  (scaled by 1/sig_p)
__device__ __half d_gT_h[BATCH * CV * TT];     // [b][c][t]  fp16 transposed (1/sig_g)

// ---------------- helpers ----------------
__device__ __forceinline__ u32 h2u(float a, float b) {
    __half2 h = __floats2half2_rn(a, b);
    return *reinterpret_cast<u32*>(&h);
}
__device__ __forceinline__ u32 smem_u32(const void* p) {
    u32 a;
    asm("{ .reg .u64 t; cvta.to.shared.u64 t, %1; cvt.u32.u64 %0, t; }" : "=r"(a) : "l"(p));
    return a;
}
__device__ __forceinline__ float ex2f(float x) {
    float r; asm("ex2.approx.ftz.f32 %0, %1;" : "=f"(r) : "f"(x)); return r;
}

// fp16 mma m16n8k16, f32 accumulate
__device__ __forceinline__ void mmaf16(float c[4], const u32 a[4], u32 b0, u32 b1) {
    asm("mma.sync.aligned.m16n8k16.row.col.f32.f16.f16.f32 "
        "{%0,%1,%2,%3}, {%4,%5,%6,%7}, {%8,%9}, {%0,%1,%2,%3};"
        : "+f"(c[0]), "+f"(c[1]), "+f"(c[2]), "+f"(c[3])
        : "r"(a[0]), "r"(a[1]), "r"(a[2]), "r"(a[3]), "r"(b0), "r"(b1));
}
__device__ __forceinline__ void ldm4(u32& r0, u32& r1, u32& r2, u32& r3, u32 addr) {
    asm volatile("ldmatrix.sync.aligned.m8n8.x4.shared.b16 {%0,%1,%2,%3}, [%4];"
                 : "=r"(r0), "=r"(r1), "=r"(r2), "=r"(r3) : "r"(addr));
}
__device__ __forceinline__ void ldm4t(u32& r0, u32& r1, u32& r2, u32& r3, u32 addr) {
    asm volatile("ldmatrix.sync.aligned.m8n8.x4.trans.shared.b16 {%0,%1,%2,%3}, [%4];"
                 : "=r"(r0), "=r"(r1), "=r"(r2), "=r"(r3) : "r"(addr));
}

__device__ __forceinline__ void cp16(u32 dst, const void* src) {
    asm volatile("cp.async.ca.shared.global [%0], [%1], 16;" :: "r"(dst), "l"(src));
}
__device__ __forceinline__ void cp_commit() { asm volatile("cp.async.commit_group;"); }
__device__ __forceinline__ void cp_wait0() { asm volatile("cp.async.wait_group 0;" ::: "memory"); }

// ---------------- spectral norm device routine (sigma only) ----------------
__device__ __forceinline__ float block_sum_128(float v, float* sred) {
    int lane = threadIdx.x & 31, w = threadIdx.x >> 5;
    v += __shfl_xor_sync(0xffffffffu, v, 16);
    v += __shfl_xor_sync(0xffffffffu, v, 8);
    v += __shfl_xor_sync(0xffffffffu, v, 4);
    v += __shfl_xor_sync(0xffffffffu, v, 2);
    v += __shfl_xor_sync(0xffffffffu, v, 1);
    if (lane == 0) sred[w] = v;
    __syncthreads();
    float r = sred[0] + sred[1] + sred[2] + sred[3];
    __syncthreads();
    return r;
}

template <int O, int I>
__device__ __forceinline__ float sn_sigma(const float* __restrict__ W,
                                          const float* __restrict__ u,
                                          float* sW, float* su, float* sv, float* sred) {
    const int t = threadIdx.x & 127;   // first 128 threads do the work
    const int S = I + 5;
    if (t < O) su[t] = u[t];
    #pragma unroll
    for (int k4 = t; k4 < O * I / 4; k4 += 128) {
        int row = k4 / (I / 4), c4 = k4 % (I / 4);
        float4 wv = ((const float4*)W)[k4];
        float* dst = &sW[row * S + c4 * 4];
        dst[0] = wv.x; dst[1] = wv.y; dst[2] = wv.z; dst[3] = wv.w;
    }
    __syncthreads();
    float vr = 0.f;
    if (t < I) {
        #pragma unroll
        for (int o = 0; o < O; o++) vr += su[o] * sW[o * S + t];
    }
    float nv2 = block_sum_128((t < I) ? vr * vr : 0.f, sred);
    float inv = 1.f / fmaxf(sqrtf(nv2), 1e-12f);
    if (t < I) sv[t] = vr * inv;
    __syncthreads();
    float ur = 0.f;
    if (t < O) {
        #pragma unroll
        for (int i = 0; i < I; i++) ur += sv[i] * sW[t * S + i];
    }
    float nu2 = block_sum_128((t < O) ? ur * ur : 0.f, sred);
    float invu = 1.f / fmaxf(sqrtf(nu2), 1e-12f);
    return block_sum_128((t < O) ? ur * ur * invu : 0.f, sred);
}

// ---------------- fused: sn (blocks 0-3) | input conv (blocks 4..515) ----------------
#define XROW 272
#define SM_X 0
#define SM_W (128 * XROW)
#define CONV_SMEM (SM_W + 96 * XROW)   // 60928 B (>= 9216 floats needed by sn path)

__global__ __launch_bounds__(256) void fusedconv_kernel(
        const float* __restrict__ x,
        const float* __restrict__ w_theta, const float* __restrict__ w_phi,
        const float* __restrict__ w_g,     const float* __restrict__ w_o,
        const float* __restrict__ u_theta, const float* __restrict__ u_phi,
        const float* __restrict__ u_g,     const float* __restrict__ u_o) {
    extern __shared__ char smc[];
    const int tid = threadIdx.x;

    // ---- sigma blocks ----
    if (blockIdx.x < 4) {
        float* sm = (float*)smc;
        float* sW = sm;                 // up to 8832 floats
        float* su = sm + 8832;
        float* sv = sm + 8832 + 128;
        float* sred = sm + 8832 + 256;
        if (tid < 128) {
            float sigma;
            switch (blockIdx.x) {
                case 0:  sigma = sn_sigma<CQ, CH>(w_theta, u_theta, sW, su, sv, sred); break;
                case 1:  sigma = sn_sigma<CQ, CH>(w_phi,   u_phi,   sW, su, sv, sred); break;
                case 2:  sigma = sn_sigma<CV, CH>(w_g,     u_g,     sW, su, sv, sred); break;
                default: sigma = sn_sigma<CH, CV>(w_o,     u_o,     sW, su, sv, sred); break;
            }
            if (tid == 0) {
                ((volatile float*)g_sig)[blockIdx.x] = sigma;
                __threadfence();
            }
        }
        return;
    }

    // ---- conv blocks ----
    const u32 sXu = smem_u32(smc) + SM_X;
    const u32 sWu = smem_u32(smc) + SM_W;
    const int w = tid >> 5, lane = tid & 31;
    const int cb = blockIdx.x - 4;
    const int b = cb >> 5, j = cb & 31;
    const int s0 = j * 128;

    // stage RAW weights (unscaled) -> fp16
    for (int i = tid; i < 96 * 16; i += 256) {
        int out = i >> 4, seg = i & 15;
        const float* src;
        if (out < 16)      src = w_theta + out * CH + seg * 8;
        else if (out < 32) src = w_phi + (out - 16) * CH + seg * 8;
        else               src = w_g + (out - 32) * CH + seg * 8;
        float4 f0 = *(const float4*)src;
        float4 f1 = *(const float4*)(src + 4);
        uint4 v = make_uint4(h2u(f0.x, f0.y), h2u(f0.z, f0.w),
                             h2u(f1.x, f1.y), h2u(f1.z, f1.w));
        asm volatile("st.shared.v4.b32 [%0], {%1,%2,%3,%4};"
                     :: "r"(sWu + (u32)(out * XROW + seg * 16)),
                        "r"(v.x), "r"(v.y), "r"(v.z), "r"(v.w) : "memory");
    }
    for (int i = tid; i < 128 * 32; i += 256) {
        int ch = i >> 5, seg = i & 31;
        float4 f = *(const float4*)&x[((size_t)b * CH + ch) * HW + s0 + seg * 4];
        u32 h0 = h2u(f.x, f.y), h1 = h2u(f.z, f.w);
        asm volatile("st.shared.v2.b32 [%0], {%1,%2};"
                     :: "r"(sXu + (u32)(ch * XROW + seg * 8)), "r"(h0), "r"(h1) : "memory");
    }
    __syncthreads();

    const int jj = lane & 7, grp = lane >> 3;
    const u32 aBase = sXu + (u32)((((grp & 2) ? 8 : 0) + jj) * XROW
                                  + (16 * w + ((grp & 1) ? 8 : 0)) * 2);
    u32 bBase[6];
    #pragma unroll
    for (int np = 0; np < 6; np++)
        bBase[np] = sWu + (u32)((np * 16 + ((grp >> 1) ? 8 : 0) + jj) * XROW
                                + ((grp & 1) ? 16 : 0));

    float c[12][4];
    #pragma unroll
    for (int nt = 0; nt < 12; nt++)
        c[nt][0] = c[nt][1] = c[nt][2] = c[nt][3] = 0.f;

    #pragma unroll
    for (int t = 0; t < 8; t++) {
        u32 a[4];
        ldm4t(a[0], a[1], a[2], a[3], aBase + (u32)(t * 16 * XROW));
        #pragma unroll
        for (int np = 0; np < 6; np++) {
            u32 b0, b1, b2, b3;
            ldm4(b0, b1, b2, b3, bBase[np] + (u32)(t * 32));
            mmaf16(c[2 * np],     a, b0, b1);
            mmaf16(c[2 * np + 1], a, b2, b3);
        }
    }

    // wait for sigmas (blocks 0-2) -- usually already done
    if (tid < 3) {
        while (((volatile float*)g_sig)[tid] == 0.f) {}
    }
    __syncthreads();
    const float sc_t = LOG2E / ((volatile float*)g_sig)[0];   // theta also folds log2e
    const float sc_p = 1.f / ((volatile float*)g_sig)[1];
    const float sc_g = 1.f / ((volatile float*)g_sig)[2];

    const int g = lane >> 2, l = lane & 3;
    const int pxA = 16 * w + g;
    #pragma unroll
    for (int nt = 0; nt < 12; nt++) {
        int np = nt >> 1;
        float sc = (np == 0) ? sc_t : (np == 1) ? sc_p : sc_g;
        u32 lo = h2u(c[nt][0] * sc, c[nt][1] * sc);
        u32 hi = h2u(c[nt][2] * sc, c[nt][3] * sc);
        asm volatile("st.shared.b32 [%0], %1;"
                     :: "r"(sXu + (u32)((pxA * 104 + nt * 8 + 2 * l) * 2)), "r"(lo) : "memory");
        asm volatile("st.shared.b32 [%0], %1;"
                     :: "r"(sXu + (u32)(((pxA + 8) * 104 + nt * 8 + 2 * l) * 2)), "r"(hi) : "memory");
    }
    __syncthreads();

    const __half* sCh = (const __half*)smc;
    {
        int px = tid >> 1, h = tid & 1;
        uint4 v = *(const uint4*)(sCh + px * 104 + h * 8);
        *(uint4*)&d_theta_h[((size_t)b * HW + s0 + px) * CQ + h * 8] = v;
    }
    if (tid < 64) {
        int wp = tid >> 1, h = tid & 1;
        int off = 16 + h * 8;
        const __half2* p0 = (const __half2*)(sCh + (2 * wp) * 104 + off);
        const __half2* p1 = (const __half2*)(sCh + (2 * wp + 1) * 104 + off);
        const __half2* p2 = (const __half2*)(sCh + (64 + 2 * wp) * 104 + off);
        const __half2* p3 = (const __half2*)(sCh + (65 + 2 * wp) * 104 + off);
        __half2 r[4];
        #pragma unroll
        for (int k = 0; k < 4; k++)
            r[k] = __hmax2(__hmax2(p0[k], p1[k]), __hmax2(p2[k], p3[k]));
        *(uint4*)&d_phi_h[((size_t)b * TT + j * 32 + wp) * CQ + h * 8] = *(uint4*)r;
    }
    if (tid < 128) {
        int ch = tid >> 1, wh = (tid & 1) * 16;
        __half2 outv[8];
        #pragma unroll
        for (int k2 = 0; k2 < 8; k2++) {
            __half v[2];
            #pragma unroll
            for (int u = 0; u < 2; u++) {
                int wp = wh + k2 * 2 + u;
                __half a0 = sCh[(2 * wp) * 104 + 32 + ch];
                __half a1 = sCh[(2 * wp + 1) * 104 + 32 + ch];
                __half a2 = sCh[(64 + 2 * wp) * 104 + 32 + ch];
                __half a3 = sCh[(65 + 2 * wp) * 104 + 32 + ch];
                v[u] = __hmax(__hmax(a0, a1), __hmax(a2, a3));
            }
            outv[k2] = __halves2half2(v[0], v[1]);
        }
        __half* dst = &d_gT_h[((size_t)b * CV + ch) * TT + j * 32 + wh];
        #pragma unroll
        for (int k2 = 0; k2 < 8; k2++) ((__half2*)dst)[k2] = outv[k2];
    }
}

// ---- attention + fused output conv + residual --------------------------------
#define KSW 8
#define VSW 36
#define KSTG (64 * KSW)
#define VSTG (64 * VSW)
#define OROWB 144
#define ATTN_SMEM_BYTES (2 * KSTG * 4 + 2 * VSTG * 4 + 128 * OROWB)  // 40960

__global__ __launch_bounds__(256, 2) void attn_fused_kernel(const float* __restrict__ x,
                                                            const float* __restrict__ w_o,
                                                            const float* __restrict__ gptr,
                                                            float* __restrict__ out) {
    __shared__ __align__(16) char sbuf[ATTN_SMEM_BYTES];
    u32* sK = (u32*)sbuf;
    u32* sV = sK + 2 * KSTG;
    const u32 kbase = smem_u32(sbuf);
    const u32 vbase = kbase + 2 * KSTG * 4;
    const u32 wobase = kbase + 2 * KSTG * 4 + 2 * VSTG * 4;
    float* sB = (float*)sbuf;   // bounce, overlays sK+sV after mainloop

    const int tid = threadIdx.x;
    const int w = tid >> 5, lane = tid & 31;
    const int g = lane >> 2, l = lane & 3;
    const int qbase = blockIdx.x * 128 + w * 16;
    const int b = (int)((blockIdx.x * 128) >> 12);
    const int s0 = (blockIdx.x * 128) & 4095;
    const __half* phib = &d_phi_h[(size_t)(b << 10) * CQ];
    const __half* gTb  = &d_gT_h[(size_t)b * CV * TT];

    // fill Wo smem (RAW weights): [128 out][64 k] f32 -> fp16
    for (int i = tid; i < 128 * 8; i += 256) {
        int o8 = i >> 3, seg = i & 7;
        const float* src = w_o + o8 * CV + seg * 8;
        float4 f0 = *(const float4*)src;
        float4 f1 = *(const float4*)(src + 4);
        uint4 v = make_uint4(h2u(f0.x, f0.y), h2u(f0.z, f0.w),
                             h2u(f1.x, f1.y), h2u(f1.z, f1.w));
        asm volatile("st.shared.v4.b32 [%0], {%1,%2,%3,%4};"
                     :: "r"(wobase + (u32)(o8 * OROWB + seg * 16)),
                        "r"(v.x), "r"(v.y), "r"(v.z), "r"(v.w) : "memory");
    }

    u32 qh[4];
    {
        const u32* q0 = (const u32*)&d_theta_h[(size_t)(qbase + g) * CQ];
        const u32* q1 = (const u32*)&d_theta_h[(size_t)(qbase + g + 8) * CQ];
        qh[0] = q0[l];     qh[1] = q1[l];
        qh[2] = q0[l + 4]; qh[3] = q1[l + 4];
    }

    float o[8][4];
    #pragma unroll
    for (int nt = 0; nt < 8; nt++)
        #pragma unroll
        for (int jj = 0; jj < 4; jj++) o[nt][jj] = 0.f;
    float mA = NEG_INF, mB = NEG_INF, lA = 0.f, lB = 0.f;

    auto fill = [&](int stage, int c0) {
        if (tid < 128) {
            int row = tid >> 1, part = tid & 1;
            cp16(kbase + (u32)((stage * KSTG + row * KSW + part * 4) * 4),
                 phib + (c0 + row) * CQ + part * 8);
        }
        #pragma unroll
        for (int i = 0; i < 2; i++) {
            int idx = tid * 2 + i;
            int c = idx >> 3, t8 = idx & 7;
            cp16(vbase + (u32)((stage * VSTG + c * VSW + t8 * 4) * 4),
                 gTb + (size_t)c * TT + c0 + t8 * 8);
        }
        cp_commit();
    };

    fill(0, 0);
    cp_wait0();
    __syncthreads();

    for (int c0 = 0; c0 < TT; c0 += 64) {
        int stage = (c0 >> 6) & 1;
        const u32* cK = sK + stage * KSTG;
        const u32* cV = sV + stage * VSTG;

        if (c0 + 64 < TT) fill(stage ^ 1, c0 + 64);

        float c[8][4];
        #pragma unroll
        for (int nt = 0; nt < 8; nt++) {
            c[nt][0] = c[nt][1] = c[nt][2] = c[nt][3] = 0.f;
            int kr = (nt * 8 + g) * KSW;
            mmaf16(c[nt], qh, cK[kr + l], cK[kr + l + 4]);
        }

        float cmA = NEG_INF, cmB = NEG_INF;
        #pragma unroll
        for (int nt = 0; nt < 8; nt++) {
            cmA = fmaxf(cmA, fmaxf(c[nt][0], c[nt][1]));
            cmB = fmaxf(cmB, fmaxf(c[nt][2], c[nt][3]));
        }
        cmA = fmaxf(cmA, __shfl_xor_sync(0xffffffffu, cmA, 1));
        cmA = fmaxf(cmA, __shfl_xor_sync(0xffffffffu, cmA, 2));
        cmB = fmaxf(cmB, __shfl_xor_sync(0xffffffffu, cmB, 1));
        cmB = fmaxf(cmB, __shfl_xor_sync(0xffffffffu, cmB, 2));
        float nmA = fmaxf(mA, cmA), nmB = fmaxf(mB, cmB);
        float sA = ex2f(mA - nmA), sB2 = ex2f(mB - nmB);
        mA = nmA; mB = nmB;
        lA *= sA; lB *= sB2;

        u32 pa[4][4];
        #pragma unroll
        for (int nt = 0; nt < 8; nt++) {
            o[nt][0] *= sA; o[nt][1] *= sA; o[nt][2] *= sB2; o[nt][3] *= sB2;
            float p0 = ex2f(c[nt][0] - mA);
            float p1 = ex2f(c[nt][1] - mA);
            float p2 = ex2f(c[nt][2] - mB);
            float p3 = ex2f(c[nt][3] - mB);
            lA += p0 + p1; lB += p2 + p3;
            int kb = nt >> 1, hi = nt & 1;
            pa[kb][hi * 2]     = h2u(p0, p1);
            pa[kb][hi * 2 + 1] = h2u(p2, p3);
        }

        #pragma unroll
        for (int kb = 0; kb < 4; kb++) {
            #pragma unroll
            for (int nt = 0; nt < 8; nt++) {
                int vr = (nt * 8 + g) * VSW + kb * 8 + l;
                mmaf16(o[nt], pa[kb], cV[vr], cV[vr + 4]);
            }
        }

        cp_wait0();
        __syncthreads();
    }

    // ---- normalize o, build fp16 A-fragments ----
    lA += __shfl_xor_sync(0xffffffffu, lA, 1);
    lA += __shfl_xor_sync(0xffffffffu, lA, 2);
    lB += __shfl_xor_sync(0xffffffffu, lB, 1);
    lB += __shfl_xor_sync(0xffffffffu, lB, 2);
    float iA = 1.f / lA, iB = 1.f / lB;
    u32 a2[4][4];
    #pragma unroll
    for (int kb = 0; kb < 4; kb++) {
        a2[kb][0] = h2u(o[2*kb][0] * iA,     o[2*kb][1] * iA);
        a2[kb][1] = h2u(o[2*kb][2] * iB,     o[2*kb][3] * iB);
        a2[kb][2] = h2u(o[2*kb + 1][0] * iA, o[2*kb + 1][1] * iA);
        a2[kb][3] = h2u(o[2*kb + 1][2] * iB, o[2*kb + 1][3] * iB);
    }

    // ---- fused output conv: out = (gamma/sigma_o) * (o_norm @ Wo_raw^T) + x ----
    const float gamma = *gptr / g_sig[3];
    const int jj = lane & 7, grp = lane >> 3;
    #pragma unroll
    for (int pp = 0; pp < 4; pp++) {       // 32-out-channel groups
        float c2[4][4];
        #pragma unroll
        for (int nt = 0; nt < 4; nt++)
            c2[nt][0] = c2[nt][1] = c2[nt][2] = c2[nt][3] = 0.f;
        #pragma unroll
        for (int t = 0; t < 4; t++) {
            #pragma unroll
            for (int np = 0; np < 2; np++) {
                u32 b0, b1, b2, b3;
                u32 baddr = wobase + (u32)((pp * 32 + np * 16 + ((grp >> 1) ? 8 : 0) + jj) * OROWB
                                           + ((grp & 1) ? 16 : 0) + t * 32);
                ldm4(b0, b1, b2, b3, baddr);
                mmaf16(c2[2 * np],     a2[t], b0, b1);
                mmaf16(c2[2 * np + 1], a2[t], b2, b3);
            }
        }
        // bounce [32 ch][132] f32
        #pragma unroll
        for (int nt = 0; nt < 4; nt++) {
            int cl = (nt >> 1) * 16 + (nt & 1) * 8 + 2 * l;
            sB[cl * 132 + 16 * w + g]           = c2[nt][0];
            sB[(cl + 1) * 132 + 16 * w + g]     = c2[nt][1];
            sB[cl * 132 + 16 * w + g + 8]       = c2[nt][2];
            sB[(cl + 1) * 132 + 16 * w + g + 8] = c2[nt][3];
        }
        __syncthreads();
        // coalesced write: 32 ch x 128 px = 1024 float4
        #pragma unroll
        for (int k = 0; k < 4; k++) {
            int flat = k * 256 + tid;
            int cc = flat >> 5, pxg = flat & 31;
            float4 v = *(const float4*)&sB[cc * 132 + pxg * 4];
            size_t idx = ((size_t)(b * CH) + pp * 32 + cc) * HW + s0 + pxg * 4;
            float4 xv = *(const float4*)&x[idx];
            *(float4*)&out[idx] = make_float4(gamma * v.x + xv.x, gamma * v.y + xv.y,
                                              gamma * v.z + xv.z, gamma * v.w + xv.w);
        }
        __syncthreads();
    }
}

// ---------------- launch ----------------
extern "C" void kernel_launch(void* const* d_in, const int* in_sizes, int n_in,
                              void* d_out, int out_size) {
    const float* x       = (const float*)d_in[0];
    const float* w_theta = (const float*)d_in[1];
    const float* w_phi   = (const float*)d_in[2];
    const float* w_g     = (const float*)d_in[3];
    const float* w_o     = (const float*)d_in[4];
    const float* u_theta = (const float*)d_in[5];
    const float* u_phi   = (const float*)d_in[6];
    const float* u_g     = (const float*)d_in[7];
    const float* u_o     = (const float*)d_in[8];
    const float* gamma   = (const float*)d_in[9];
    float* out = (float*)d_out;

    cudaFuncSetAttribute(fusedconv_kernel, cudaFuncAttributeMaxDynamicSharedMemorySize, CONV_SMEM);

    fusedconv_kernel<<<516, 256, CONV_SMEM>>>(x, w_theta, w_phi, w_g, w_o,
                                              u_theta, u_phi, u_g, u_o);
    attn_fused_kernel<<<512, 256>>>(x, w_o, gamma, out);
}